// round 1
// baseline (speedup 1.0000x reference)
#include <cuda_runtime.h>
#include <cstdint>

// ---------------- problem constants ----------------
#define NN    4096      // nodes
#define BB    32        // batch
#define CC    64        // channels in/out
#define DE    16        // embedding dim
#define NBJ   2048      // B*C  (columns of the big GEMM)

// ---------------- device scratch (no allocs allowed) ----------------
__device__ float g_S [ (size_t)NN * NN ];      // dynamic support, 64 MB
__device__ float g_XT[ (size_t)NN * NBJ ];     // x transposed to [m][b*64+c], 32 MB
__device__ float g_Y [ (size_t)NN * NBJ ];     // S @ XT, 32 MB
__device__ float g_W [ (size_t)NN * 8192 ];    // per-node weights [n][k*4096+i*64+o], 134 MB
__device__ float g_sd[ NN ];                   // 1/sqrt(rowsum(adj+0.5I))
__device__ float g_scale[ NN ];                // column sums of double-softmaxed A

// ---------------- reductions ----------------
__device__ __forceinline__ float warpSum(float v){
#pragma unroll
    for (int o = 16; o; o >>= 1) v += __shfl_xor_sync(0xffffffffu, v, o);
    return v;
}
__device__ __forceinline__ float warpMax(float v){
#pragma unroll
    for (int o = 16; o; o >>= 1) v = fmaxf(v, __shfl_xor_sync(0xffffffffu, v, o));
    return v;
}
// blockDim.x == 256 assumed (8 warps)
__device__ __forceinline__ float blockSum(float v, float* red){
    v = warpSum(v);
    int lane = threadIdx.x & 31, w = threadIdx.x >> 5;
    if (lane == 0) red[w] = v;
    __syncthreads();
    float r = 0.f;
#pragma unroll
    for (int i = 0; i < 8; i++) r += red[i];
    __syncthreads();
    return r;
}
__device__ __forceinline__ float blockMax(float v, float* red){
    v = warpMax(v);
    int lane = threadIdx.x & 31, w = threadIdx.x >> 5;
    if (lane == 0) red[w] = v;
    __syncthreads();
    float r = -3.0e38f;
#pragma unroll
    for (int i = 0; i < 8; i++) r = fmaxf(r, red[i]);
    __syncthreads();
    return r;
}

// ---------------- 0: zero the scale accumulator ----------------
__global__ void k_zero(){
    int i = blockIdx.x * 256 + threadIdx.x;
    if (i < NN) g_scale[i] = 0.f;
}

// ---------------- 1: rowsums of (adj + 0.5 I) -> g_sd ----------------
__global__ __launch_bounds__(256) void k_rowsum(const float* __restrict__ adj){
    __shared__ float red[8];
    int n = blockIdx.x;
    const float* row = adj + (size_t)n * NN;
    float s = 0.f;
    for (int m = threadIdx.x; m < NN; m += 256) s += row[m];
    if (threadIdx.x == 0) s += 0.5f;   // diagonal add
    s = blockSum(s, red);
    if (threadIdx.x == 0) g_sd[n] = rsqrtf(s);
}

// ---------------- 2: double row-softmax of sym-normed adj, column sums ----------------
// 16 rows per block; acc[m] owned by thread (m % 256 == tid) -> race-free smem adds.
__global__ __launch_bounds__(256) void k_scale(const float* __restrict__ adj){
    __shared__ float rowbuf[NN];
    __shared__ float acc[NN];
    __shared__ float red[8];
    int tid = threadIdx.x;
    for (int m = tid; m < NN; m += 256) acc[m] = 0.f;
    for (int r = 0; r < 16; r++){
        int n = blockIdx.x * 16 + r;
        const float* row = adj + (size_t)n * NN;
        float sdn = g_sd[n];
        float lmax = -3.0e38f;
        for (int m = tid; m < NN; m += 256){
            float w = row[m] + ((m == n) ? 0.5f : 0.f);
            float v = sdn * w * g_sd[m];
            rowbuf[m] = v;
            lmax = fmaxf(lmax, v);
        }
        float bm = blockMax(lmax, red);
        float ls = 0.f;
        for (int m = tid; m < NN; m += 256){
            float e = __expf(rowbuf[m] - bm);
            rowbuf[m] = e; ls += e;
        }
        float inv = 1.f / blockSum(ls, red);
        // after 1st softmax: values a = e*inv, and max(e)==exp(0)==1 -> max(a)==inv
        float ls2 = 0.f;
        for (int m = tid; m < NN; m += 256){
            float e2 = __expf(fmaf(rowbuf[m], inv, -inv));
            rowbuf[m] = e2; ls2 += e2;
        }
        float inv2 = 1.f / blockSum(ls2, red);
        for (int m = tid; m < NN; m += 256) acc[m] += rowbuf[m] * inv2;
    }
    __syncthreads();
    for (int m = tid; m < NN; m += 256) atomicAdd(&g_scale[m], acc[m]);
}

// ---------------- 3: dynamic support S = softmax(relu(E E^T)) row-wise ----------------
// 2 rows per block (32 KB row buffers, static-smem safe).
__global__ __launch_bounds__(256) void k_dyn(const float* __restrict__ E){
    __shared__ float rowbuf[2][NN];
    __shared__ float er[2][DE];
    __shared__ float red[8];
    int tid = threadIdx.x;
    int n0 = blockIdx.x * 2;
    if (tid < 2 * DE) er[tid / DE][tid % DE] = E[(n0 + tid / DE) * DE + (tid % DE)];
    __syncthreads();
    float lmax0 = 0.f, lmax1 = 0.f;   // relu >= 0
    for (int m = tid; m < NN; m += 256){
        const float4* ep = (const float4*)(E + (size_t)m * DE);
        float4 e0 = ep[0], e1 = ep[1], e2 = ep[2], e3 = ep[3];
        float em[16] = { e0.x,e0.y,e0.z,e0.w, e1.x,e1.y,e1.z,e1.w,
                         e2.x,e2.y,e2.z,e2.w, e3.x,e3.y,e3.z,e3.w };
        float d0 = 0.f, d1 = 0.f;
#pragma unroll
        for (int d = 0; d < DE; d++){ d0 += em[d] * er[0][d]; d1 += em[d] * er[1][d]; }
        float v0 = fmaxf(d0, 0.f), v1 = fmaxf(d1, 0.f);
        rowbuf[0][m] = v0; rowbuf[1][m] = v1;
        lmax0 = fmaxf(lmax0, v0); lmax1 = fmaxf(lmax1, v1);
    }
#pragma unroll
    for (int r = 0; r < 2; r++){
        float bm = blockMax(r == 0 ? lmax0 : lmax1, red);
        float ls = 0.f;
        for (int m = tid; m < NN; m += 256){
            float e = __expf(rowbuf[r][m] - bm);
            rowbuf[r][m] = e; ls += e;
        }
        float inv = 1.f / blockSum(ls, red);
        float* out = g_S + (size_t)(n0 + r) * NN;
        for (int m = tid; m < NN; m += 256) out[m] = rowbuf[r][m] * inv;
    }
}

// ---------------- 4: transpose x [B,N,C] -> XT [N, B*C] ----------------
__global__ void k_transpose(const float* __restrict__ x){
    int idx = blockIdx.x * 256 + threadIdx.x;       // float4 index, 2097152 total
    int c4 = idx & 15;
    int b  = (idx >> 4) & 31;
    int m  = idx >> 9;
    float4 v = ((const float4*)x)[(size_t)(b * NN + m) * 16 + c4];
    ((float4*)g_XT)[idx] = v;
}

// ---------------- 5: per-node weights g_W[n][k*4096+i*64+o] = sum_d E[n,d] wp[d,...] ----
// Block covers 128 nodes x 512-wide wp chunk; wp chunk cached in smem.
__global__ __launch_bounds__(256) void k_wgen(const float* __restrict__ E,
                                              const float* __restrict__ wp){
    __shared__ float wpc[DE * 512];
    __shared__ float es[128 * DE];
    int tid = threadIdx.x;
    int c0 = blockIdx.x * 512;
    int n0 = blockIdx.y * 128;
    for (int t = tid; t < DE * 512; t += 256){
        int d = t >> 9, j = t & 511;
        wpc[t] = wp[(size_t)d * 8192 + c0 + j];
    }
    for (int t = tid; t < 128 * DE; t += 256) es[t] = E[(size_t)n0 * DE + t];
    __syncthreads();
    for (int t = tid; t < 128 * 512; t += 256){
        int nl = t >> 9, j = t & 511;
        float s = 0.f;
#pragma unroll
        for (int d = 0; d < DE; d++) s += es[nl * DE + d] * wpc[d * 512 + j];
        g_W[(size_t)(n0 + nl) * 8192 + c0 + j] = s;
    }
}

// ---------------- 6: the big GEMM  Y = S @ XT  (4096 x 2048 x 4096, fp32) ----------------
// Classic 128x128x8, 256 threads, 8x8 microtile, double-buffered smem.
__global__ __launch_bounds__(256, 2) void k_gemm(){
    const int M = NN, Nj = NBJ, K = NN;
    __shared__ float As[2][8][128];
    __shared__ float Bs[2][8][128];
    int tid = threadIdx.x;
    int arow = tid >> 1;              // 0..127
    int acol = (tid & 1) << 2;        // 0 or 4
    int brow = tid >> 5;              // 0..7
    int bcol = (tid & 31) << 2;       // 0..124
    const float* Ag = g_S  + (size_t)(blockIdx.y * 128 + arow) * K + acol;
    const float* Bg = g_XT + (size_t)brow * Nj + blockIdx.x * 128 + bcol;

    // preload tile 0
    float4 a = *(const float4*)Ag;
    float4 b = *(const float4*)Bg;
    As[0][acol + 0][arow] = a.x; As[0][acol + 1][arow] = a.y;
    As[0][acol + 2][arow] = a.z; As[0][acol + 3][arow] = a.w;
    *(float4*)&Bs[0][brow][bcol] = b;
    __syncthreads();

    int tx = tid & 15, ty = tid >> 4;
    float acc[8][8];
#pragma unroll
    for (int i = 0; i < 8; i++)
#pragma unroll
        for (int j = 0; j < 8; j++) acc[i][j] = 0.f;

    int buf = 0;
    for (int kt = 8; kt <= K; kt += 8){
        float4 an, bn;
        bool more = kt < K;
        if (more){
            an = *(const float4*)(Ag + kt);
            bn = *(const float4*)(Bg + (size_t)kt * Nj);
        }
#pragma unroll
        for (int kk = 0; kk < 8; kk++){
            float4 a0 = *(float4*)&As[buf][kk][ty * 8];
            float4 a1 = *(float4*)&As[buf][kk][ty * 8 + 4];
            float4 b0 = *(float4*)&Bs[buf][kk][tx * 8];
            float4 b1 = *(float4*)&Bs[buf][kk][tx * 8 + 4];
            float ar[8] = {a0.x,a0.y,a0.z,a0.w,a1.x,a1.y,a1.z,a1.w};
            float br[8] = {b0.x,b0.y,b0.z,b0.w,b1.x,b1.y,b1.z,b1.w};
#pragma unroll
            for (int i = 0; i < 8; i++)
#pragma unroll
                for (int j = 0; j < 8; j++)
                    acc[i][j] = fmaf(ar[i], br[j], acc[i][j]);
        }
        if (more){
            As[buf ^ 1][acol + 0][arow] = an.x; As[buf ^ 1][acol + 1][arow] = an.y;
            As[buf ^ 1][acol + 2][arow] = an.z; As[buf ^ 1][acol + 3][arow] = an.w;
            *(float4*)&Bs[buf ^ 1][brow][bcol] = bn;
            __syncthreads();
            buf ^= 1;
        }
    }
    float* Cp = g_Y + (size_t)(blockIdx.y * 128 + ty * 8) * Nj + blockIdx.x * 128 + tx * 8;
#pragma unroll
    for (int i = 0; i < 8; i++){
        *(float4*)(Cp + (size_t)i * Nj)     = make_float4(acc[i][0], acc[i][1], acc[i][2], acc[i][3]);
        *(float4*)(Cp + (size_t)i * Nj + 4) = make_float4(acc[i][4], acc[i][5], acc[i][6], acc[i][7]);
    }
}

// ---------------- 7: static branch  out = sigmoid(xs)*xs ----------------
// xs[bn,o] = scale[n] * dot(x[bn,:], lin_w[o,:]) + lin_b[o]; 32 bn-rows per block.
__global__ __launch_bounds__(256) void k_static(const float* __restrict__ x,
                                                const float* __restrict__ lw,
                                                const float* __restrict__ lb,
                                                float* __restrict__ out){
    __shared__ float LW[CC * CC];     // LW[i*64+o] = lw[o*64+i]
    __shared__ float xt[32][CC];
    __shared__ float lbs[CC];
    int tid = threadIdx.x;
    for (int idx = tid; idx < CC * CC; idx += 256){
        int o = idx & 63, i = idx >> 6;
        LW[i * 64 + o] = lw[o * 64 + i];
    }
    if (tid < CC) lbs[tid] = lb[tid];
    size_t row0 = (size_t)blockIdx.x * 32;
    for (int idx = tid; idx < 512; idx += 256){
        int r = idx >> 4, i4 = idx & 15;
        ((float4*)&xt[r][0])[i4] = *(const float4*)&x[(row0 + r) * 64 + i4 * 4];
    }
    __syncthreads();
    int o = tid & 63, rq = tid >> 6;       // rq: 0..3 -> rows rq*8..rq*8+7
    float accv[8];
#pragma unroll
    for (int t = 0; t < 8; t++) accv[t] = 0.f;
    for (int i = 0; i < CC; i++){
        float w = LW[i * 64 + o];
#pragma unroll
        for (int t = 0; t < 8; t++) accv[t] = fmaf(xt[rq * 8 + t][i], w, accv[t]);
    }
#pragma unroll
    for (int t = 0; t < 8; t++){
        size_t r = row0 + rq * 8 + t;
        int n = (int)(r & (NN - 1));
        float xs = g_scale[n] * accv[t] + lbs[o];
        float sg = 1.f / (1.f + __expf(-xs));
        out[r * 64 + o] = sg * xs;
    }
}

// ---------------- 8: gconv  out += x@W0 + Y@W1 + bias(n) ----------------
// One block per node. W (32 KB) in smem; two 16-batch passes with x/Y tiles.
__global__ __launch_bounds__(256) void k_final(const float* __restrict__ x,
                                               const float* __restrict__ E,
                                               const float* __restrict__ bp,
                                               float* __restrict__ out){
    __shared__ float W[8192];
    __shared__ float4 Xs[16][16];
    __shared__ float4 Ys[16][16];
    __shared__ float bias_s[CC];
    __shared__ float e_s[DE];
    int n = blockIdx.x, tid = threadIdx.x;
    if (tid < DE) e_s[tid] = E[(size_t)n * DE + tid];
    __syncthreads();
    {   // copy precomputed W row (coalesced float4)
        const float4* src = (const float4*)(g_W + (size_t)n * 8192);
        for (int t = tid; t < 2048; t += 256) ((float4*)W)[t] = src[t];
    }
    if (tid < CC){
        float s = 0.f;
#pragma unroll
        for (int d = 0; d < DE; d++) s += e_s[d] * bp[d * 64 + tid];
        bias_s[tid] = s;
    }
    __syncthreads();
    int o = tid & 63, g = tid >> 6;        // g: 0..3
    for (int pass = 0; pass < 2; pass++){
        int bbase = pass * 16;
        __syncthreads();                    // protect previous pass's readers
        {
            int b = tid >> 4, i4 = tid & 15;
            Xs[b][i4] = *(const float4*)&x[((size_t)(bbase + b) * NN + n) * 64 + i4 * 4];
            Ys[b][i4] = *(const float4*)&g_Y[(size_t)n * NBJ + (bbase + b) * 64 + i4 * 4];
        }
        __syncthreads();
        float acc[4] = {0.f, 0.f, 0.f, 0.f};
#pragma unroll 4
        for (int i4 = 0; i4 < 16; i4++){
            int ib = i4 * 4;
            float w00 = W[(ib + 0) * 64 + o], w01 = W[(ib + 1) * 64 + o];
            float w02 = W[(ib + 2) * 64 + o], w03 = W[(ib + 3) * 64 + o];
            float w10 = W[4096 + (ib + 0) * 64 + o], w11 = W[4096 + (ib + 1) * 64 + o];
            float w12 = W[4096 + (ib + 2) * 64 + o], w13 = W[4096 + (ib + 3) * 64 + o];
#pragma unroll
            for (int t = 0; t < 4; t++){
                float4 xv = Xs[g + 4 * t][i4];
                float4 yv = Ys[g + 4 * t][i4];
                float a = acc[t];
                a = fmaf(xv.x, w00, a); a = fmaf(xv.y, w01, a);
                a = fmaf(xv.z, w02, a); a = fmaf(xv.w, w03, a);
                a = fmaf(yv.x, w10, a); a = fmaf(yv.y, w11, a);
                a = fmaf(yv.z, w12, a); a = fmaf(yv.w, w13, a);
                acc[t] = a;
            }
        }
#pragma unroll
        for (int t = 0; t < 4; t++){
            int b = bbase + g + 4 * t;
            size_t oi = ((size_t)b * NN + n) * 64 + o;
            out[oi] += acc[t] + bias_s[o];
        }
    }
}

// ---------------- launch ----------------
extern "C" void kernel_launch(void* const* d_in, const int* in_sizes, int n_in,
                              void* d_out, int out_size){
    const float* x   = (const float*)d_in[0];
    const float* E   = (const float*)d_in[1];
    const float* wp  = (const float*)d_in[2];
    const float* bp  = (const float*)d_in[3];
    const float* lw  = (const float*)d_in[4];
    const float* lb  = (const float*)d_in[5];
    const float* adj = (const float*)d_in[6];
    float* out = (float*)d_out;
    (void)in_sizes; (void)n_in; (void)out_size;

    k_zero     <<<16, 256>>>();
    k_rowsum   <<<NN, 256>>>(adj);
    k_scale    <<<NN / 16, 256>>>(adj);
    k_dyn      <<<NN / 2, 256>>>(E);
    k_transpose<<<8192, 256>>>(x);
    k_wgen     <<<dim3(16, 32), 256>>>(E, wp);
    k_gemm     <<<dim3(NBJ / 128, NN / 128), 256>>>();
    k_static   <<<(BB * NN) / 32, 256>>>(x, lw, lb, out);
    k_final    <<<NN, 256>>>(x, E, bp, out);
}

// round 3
// speedup vs baseline: 1.7615x; 1.7615x over previous
#include <cuda_runtime.h>
#include <cuda_bf16.h>
#include <cstdint>

// ---------------- problem constants ----------------
#define NN    4096      // nodes
#define BB    32        // batch
#define CC    64        // channels in/out
#define DE    16        // embedding dim
#define NBJ   2048      // B*C  (columns of the big GEMM)

// ---------------- device scratch (no allocs allowed) ----------------
__device__ __align__(256) __nv_bfloat16 g_Ah[(size_t)NN * NN];    // hi(S), 32 MB
__device__ __align__(256) __nv_bfloat16 g_Al[(size_t)NN * NN];    // lo(S), 32 MB
__device__ __align__(256) __nv_bfloat16 g_Bh[(size_t)NBJ * NN];   // hi(x^T) [j][k], 16 MB
__device__ __align__(256) __nv_bfloat16 g_Bl[(size_t)NBJ * NN];   // lo(x^T), 16 MB
__device__ __align__(256) float g_Y [(size_t)NN * NBJ];           // S @ XT, 32 MB
__device__ __align__(256) float g_W [(size_t)NN * 8192];          // per-node weights, 134 MB
__device__ float g_sd[NN];
__device__ float g_scale[NN];

// ---------------- PTX helpers (base ISA only: ldmatrix / mma.sync / cp.async) --
__device__ __forceinline__ uint32_t smem_u32(const void* p){
    uint32_t a;
    asm("{ .reg .u64 t; cvta.to.shared.u64 t, %1; cvt.u32.u64 %0, t; }" : "=r"(a) : "l"(p));
    return a;
}
#define LDSM_X4(R, addr) \
    asm volatile("ldmatrix.sync.aligned.m8n8.x4.shared.b16 {%0,%1,%2,%3}, [%4];" \
        : "=r"((R)[0]), "=r"((R)[1]), "=r"((R)[2]), "=r"((R)[3]) : "r"(addr))
#define MMA16816(D, A, B0, B1) \
    asm volatile("mma.sync.aligned.m16n8k16.row.col.f32.bf16.bf16.f32 " \
        "{%0,%1,%2,%3}, {%4,%5,%6,%7}, {%8,%9}, {%0,%1,%2,%3};" \
        : "+f"((D)[0]), "+f"((D)[1]), "+f"((D)[2]), "+f"((D)[3]) \
        : "r"((A)[0]), "r"((A)[1]), "r"((A)[2]), "r"((A)[3]), "r"(B0), "r"(B1))
#define CP_ASYNC16(dst, src) \
    asm volatile("cp.async.cg.shared.global [%0], [%1], 16;" :: "r"(dst), "l"(src) : "memory")
#define CP_COMMIT() asm volatile("cp.async.commit_group;" ::: "memory")

// ---------------- reductions ----------------
__device__ __forceinline__ float warpSum(float v){
#pragma unroll
    for (int o = 16; o; o >>= 1) v += __shfl_xor_sync(0xffffffffu, v, o);
    return v;
}
__device__ __forceinline__ float warpMax(float v){
#pragma unroll
    for (int o = 16; o; o >>= 1) v = fmaxf(v, __shfl_xor_sync(0xffffffffu, v, o));
    return v;
}
__device__ __forceinline__ float blockSum(float v, float* red){
    v = warpSum(v);
    int lane = threadIdx.x & 31, w = threadIdx.x >> 5;
    if (lane == 0) red[w] = v;
    __syncthreads();
    float r = 0.f;
#pragma unroll
    for (int i = 0; i < 8; i++) r += red[i];
    __syncthreads();
    return r;
}
__device__ __forceinline__ float blockMax(float v, float* red){
    v = warpMax(v);
    int lane = threadIdx.x & 31, w = threadIdx.x >> 5;
    if (lane == 0) red[w] = v;
    __syncthreads();
    float r = -3.0e38f;
#pragma unroll
    for (int i = 0; i < 8; i++) r = fmaxf(r, red[i]);
    __syncthreads();
    return r;
}

// ---------------- 0: zero scale accumulator ----------------
__global__ void k_zero(){
    int i = blockIdx.x * 256 + threadIdx.x;
    if (i < NN) g_scale[i] = 0.f;
}

// ---------------- 1: rowsums of (adj + 0.5 I) -> g_sd ----------------
__global__ __launch_bounds__(256) void k_rowsum(const float* __restrict__ adj){
    __shared__ float red[8];
    int n = blockIdx.x;
    const float* row = adj + (size_t)n * NN;
    float s = 0.f;
    for (int m = threadIdx.x; m < NN; m += 256) s += row[m];
    if (threadIdx.x == 0) s += 0.5f;
    s = blockSum(s, red);
    if (threadIdx.x == 0) g_sd[n] = rsqrtf(s);
}

// ---------------- 2: double row-softmax of sym-normed adj, column sums ----------------
__global__ __launch_bounds__(256) void k_scale(const float* __restrict__ adj){
    __shared__ float rowbuf[NN];
    __shared__ float acc[NN];
    __shared__ float red[8];
    int tid = threadIdx.x;
    for (int m = tid; m < NN; m += 256) acc[m] = 0.f;
    for (int r = 0; r < 16; r++){
        int n = blockIdx.x * 16 + r;
        const float* row = adj + (size_t)n * NN;
        float sdn = g_sd[n];
        float lmax = -3.0e38f;
        for (int m = tid; m < NN; m += 256){
            float w = row[m] + ((m == n) ? 0.5f : 0.f);
            float v = sdn * w * g_sd[m];
            rowbuf[m] = v;
            lmax = fmaxf(lmax, v);
        }
        float bm = blockMax(lmax, red);
        float ls = 0.f;
        for (int m = tid; m < NN; m += 256){
            float e = __expf(rowbuf[m] - bm);
            rowbuf[m] = e; ls += e;
        }
        float inv = 1.f / blockSum(ls, red);
        float ls2 = 0.f;
        for (int m = tid; m < NN; m += 256){
            float e2 = __expf(fmaf(rowbuf[m], inv, -inv));
            rowbuf[m] = e2; ls2 += e2;
        }
        float inv2 = 1.f / blockSum(ls2, red);
        for (int m = tid; m < NN; m += 256) acc[m] += rowbuf[m] * inv2;
    }
    __syncthreads();
    for (int m = tid; m < NN; m += 256) atomicAdd(&g_scale[m], acc[m]);
}

// ---------------- 3: S = softmax(relu(E E^T)) -> bf16 hi/lo split ----------------
__global__ __launch_bounds__(256) void k_dyn(const float* __restrict__ E){
    __shared__ float rowbuf[2][NN];
    __shared__ float er[2][DE];
    __shared__ float red[8];
    int tid = threadIdx.x;
    int n0 = blockIdx.x * 2;
    if (tid < 2 * DE) er[tid / DE][tid % DE] = E[(n0 + tid / DE) * DE + (tid % DE)];
    __syncthreads();
    float lmax0 = 0.f, lmax1 = 0.f;
    for (int m = tid; m < NN; m += 256){
        const float4* ep = (const float4*)(E + (size_t)m * DE);
        float4 e0 = ep[0], e1 = ep[1], e2 = ep[2], e3 = ep[3];
        float em[16] = { e0.x,e0.y,e0.z,e0.w, e1.x,e1.y,e1.z,e1.w,
                         e2.x,e2.y,e2.z,e2.w, e3.x,e3.y,e3.z,e3.w };
        float d0 = 0.f, d1 = 0.f;
#pragma unroll
        for (int d = 0; d < DE; d++){ d0 += em[d] * er[0][d]; d1 += em[d] * er[1][d]; }
        float v0 = fmaxf(d0, 0.f), v1 = fmaxf(d1, 0.f);
        rowbuf[0][m] = v0; rowbuf[1][m] = v1;
        lmax0 = fmaxf(lmax0, v0); lmax1 = fmaxf(lmax1, v1);
    }
#pragma unroll
    for (int r = 0; r < 2; r++){
        float bm = blockMax(r == 0 ? lmax0 : lmax1, red);
        float ls = 0.f;
        for (int m = tid; m < NN; m += 256){
            float e = __expf(rowbuf[r][m] - bm);
            rowbuf[r][m] = e; ls += e;
        }
        float inv = 1.f / blockSum(ls, red);
        __nv_bfloat16* oh = g_Ah + (size_t)(n0 + r) * NN;
        __nv_bfloat16* ol = g_Al + (size_t)(n0 + r) * NN;
        for (int m = tid; m < NN; m += 256){
            float v = rowbuf[r][m] * inv;
            __nv_bfloat16 h = __float2bfloat16(v);
            oh[m] = h;
            ol[m] = __float2bfloat16(v - __bfloat162float(h));
        }
    }
}

// ---------------- 4: x [B,N,C] -> B-operand [j=b*64+c][k] bf16 hi/lo ----------------
__global__ __launch_bounds__(256) void k_xsplit(const float* __restrict__ x){
    __shared__ float xs[64][65];
    int b  = blockIdx.x >> 6;
    int kc = blockIdx.x & 63;
    int tid = threadIdx.x;
    const float* src = x + ((size_t)b * NN + kc * 64) * 64;
    for (int t = tid; t < 1024; t += 256){
        int kk = t >> 4, c4 = t & 15;
        float4 v = ((const float4*)src)[(size_t)kk * 16 + c4];
        xs[kk][c4 * 4 + 0] = v.x; xs[kk][c4 * 4 + 1] = v.y;
        xs[kk][c4 * 4 + 2] = v.z; xs[kk][c4 * 4 + 3] = v.w;
    }
    __syncthreads();
    int c = tid >> 2, q = tid & 3;
    union { __nv_bfloat16 h[16]; uint4 u[2]; } uh, ul;
#pragma unroll
    for (int i = 0; i < 16; i++){
        float v = xs[q * 16 + i][c];
        __nv_bfloat16 h = __float2bfloat16(v);
        uh.h[i] = h;
        ul.h[i] = __float2bfloat16(v - __bfloat162float(h));
    }
    size_t off = ((size_t)(b * 64 + c)) * NN + kc * 64 + q * 16;
    *(uint4*)(g_Bh + off) = uh.u[0]; *(uint4*)(g_Bh + off + 8) = uh.u[1];
    *(uint4*)(g_Bl + off) = ul.u[0]; *(uint4*)(g_Bl + off + 8) = ul.u[1];
}

// ---------------- 5: per-node weights ----------------
__global__ __launch_bounds__(256) void k_wgen(const float* __restrict__ E,
                                              const float* __restrict__ wp){
    __shared__ float wpc[DE * 512];
    __shared__ float es[128 * DE];
    int tid = threadIdx.x;
    int c0 = blockIdx.x * 512;
    int n0 = blockIdx.y * 128;
    for (int t = tid; t < DE * 512; t += 256){
        int d = t >> 9, j = t & 511;
        wpc[t] = wp[(size_t)d * 8192 + c0 + j];
    }
    for (int t = tid; t < 128 * DE; t += 256) es[t] = E[(size_t)n0 * DE + t];
    __syncthreads();
    for (int t = tid; t < 128 * 512; t += 256){
        int nl = t >> 9, j = t & 511;
        float s = 0.f;
#pragma unroll
        for (int d = 0; d < DE; d++) s += es[nl * DE + d] * wpc[d * 512 + j];
        g_W[(size_t)(n0 + nl) * 8192 + c0 + j] = s;
    }
}

// ---------------- 6: HMMA GEMM  Y = S @ XT  (bf16 hi/lo 3-product) ----------
// Block 128x128, warp tile 32x64 (4x2 warps), K-chunk 32, 3-stage cp.async.
// Smem tile rows padded to 80B: ldmatrix 8-row phases are bank-conflict-free.
#define STAGE_BYTES 40960           // 4 tiles x 128 rows x 80B
#define TILE_BYTES  10240
#define GEMM_SMEM   (3 * STAGE_BYTES)

__global__ __launch_bounds__(256) void k_gemm_mma(){
    extern __shared__ __align__(1024) char smem[];
    uint32_t sm = smem_u32(smem);
    int tid = threadIdx.x, wid = tid >> 5, lane = tid & 31;
    int bx = blockIdx.x, by = blockIdx.y;

    const char* pAh = (const char*)g_Ah + (size_t)(by * 128) * (NN * 2);
    const char* pAl = (const char*)g_Al + (size_t)(by * 128) * (NN * 2);
    const char* pBh = (const char*)g_Bh + (size_t)(bx * 128) * (NN * 2);
    const char* pBl = (const char*)g_Bl + (size_t)(bx * 128) * (NN * 2);

    // warp position: 4 m-warps x 2 n-warps
    int m0 = (wid & 3) * 32;
    int n0 = (wid >> 2) * 64;

    // ldmatrix lane addressing (within a tile; byte offsets)
    uint32_t a_off = (uint32_t)((m0 + (lane & 15)) * 80 + ((lane >> 4) << 4));
    uint32_t b_off = (uint32_t)((n0 + ((lane >> 4) << 3) + (lane & 7)) * 80
                                + (((lane >> 3) & 1) << 4));

    auto load_stage = [&](int buf, int kblk){
        uint32_t sbase = sm + (uint32_t)buf * STAGE_BYTES;
        size_t kb = (size_t)kblk * 64;             // 32 bf16 = 64B per row chunk
#pragma unroll
        for (int i = 0; i < 8; i++){
            int id = tid + i * 256;                // 0..2047
            int tile = id >> 9;                    // 0..3: Ah, Al, Bh, Bl
            int r = (id >> 2) & 127;
            int c = id & 3;
            const char* gb = (tile == 0) ? pAh : (tile == 1) ? pAl
                           : (tile == 2) ? pBh : pBl;
            const char* src = gb + (size_t)r * (NN * 2) + kb + (size_t)c * 16;
            uint32_t dst = sbase + (uint32_t)tile * TILE_BYTES + (uint32_t)(r * 80 + c * 16);
            CP_ASYNC16(dst, src);
        }
        CP_COMMIT();
    };

    float acc[2][8][4];
#pragma unroll
    for (int tm = 0; tm < 2; tm++)
#pragma unroll
        for (int nb = 0; nb < 8; nb++)
#pragma unroll
            for (int q = 0; q < 4; q++) acc[tm][nb][q] = 0.f;

    load_stage(0, 0);
    load_stage(1, 1);

    const int NIT = NN / 32;          // 128 iterations
    for (int s = 0; s < NIT; s++){
        if (s + 2 < NIT) asm volatile("cp.async.wait_group 1;" ::: "memory");
        else             asm volatile("cp.async.wait_group 0;" ::: "memory");
        __syncthreads();
        if (s + 2 < NIT) load_stage((s + 2) % 3, s + 2);

        uint32_t st = sm + (uint32_t)(s % 3) * STAGE_BYTES;
        uint32_t aAh = st + a_off;
        uint32_t aAl = st + TILE_BYTES + a_off;
        uint32_t aBh = st + 2 * TILE_BYTES + b_off;
        uint32_t aBl = st + 3 * TILE_BYTES + b_off;
#pragma unroll
        for (int ks = 0; ks < 2; ks++){
            uint32_t ko = (uint32_t)(ks * 32);
            uint32_t Ahf[2][4], Alf[2][4], Bhf[4][4], Blf[4][4];
            LDSM_X4(Ahf[0], aAh + ko);
            LDSM_X4(Ahf[1], aAh + 1280 + ko);       // +16 rows * 80B
            LDSM_X4(Alf[0], aAl + ko);
            LDSM_X4(Alf[1], aAl + 1280 + ko);
#pragma unroll
            for (int p = 0; p < 4; p++){
                LDSM_X4(Bhf[p], aBh + (uint32_t)(p * 1280) + ko);
                LDSM_X4(Blf[p], aBl + (uint32_t)(p * 1280) + ko);
            }
#pragma unroll
            for (int tm = 0; tm < 2; tm++)
#pragma unroll
                for (int nb = 0; nb < 8; nb++){
                    int p = nb >> 1, h = (nb & 1) * 2;
                    MMA16816(acc[tm][nb], Ahf[tm], Bhf[p][h], Bhf[p][h + 1]);
                    MMA16816(acc[tm][nb], Alf[tm], Bhf[p][h], Bhf[p][h + 1]);
                    MMA16816(acc[tm][nb], Ahf[tm], Blf[p][h], Blf[p][h + 1]);
                }
        }
    }

    // epilogue: d-frag mapping — rows lane>>2 (+8), cols (lane&3)*2 (+1)
    int gr = lane >> 2, gc = (lane & 3) * 2;
#pragma unroll
    for (int tm = 0; tm < 2; tm++){
        int row = by * 128 + m0 + tm * 16 + gr;
        float* y0 = g_Y + (size_t)row * NBJ + bx * 128 + n0 + gc;
        float* y1 = y0 + 8 * NBJ;
#pragma unroll
        for (int nb = 0; nb < 8; nb++){
            *(float2*)(y0 + nb * 8) = make_float2(acc[tm][nb][0], acc[tm][nb][1]);
            *(float2*)(y1 + nb * 8) = make_float2(acc[tm][nb][2], acc[tm][nb][3]);
        }
    }
}

// ---------------- 7: static branch ----------------
__global__ __launch_bounds__(256) void k_static(const float* __restrict__ x,
                                                const float* __restrict__ lw,
                                                const float* __restrict__ lb,
                                                float* __restrict__ out){
    __shared__ float LW[CC * CC];
    __shared__ float xt[32][CC];
    __shared__ float lbs[CC];
    int tid = threadIdx.x;
    for (int idx = tid; idx < CC * CC; idx += 256){
        int o = idx & 63, i = idx >> 6;
        LW[i * 64 + o] = lw[o * 64 + i];
    }
    if (tid < CC) lbs[tid] = lb[tid];
    size_t row0 = (size_t)blockIdx.x * 32;
    for (int idx = tid; idx < 512; idx += 256){
        int r = idx >> 4, i4 = idx & 15;
        ((float4*)&xt[r][0])[i4] = *(const float4*)&x[(row0 + r) * 64 + i4 * 4];
    }
    __syncthreads();
    int o = tid & 63, rq = tid >> 6;
    float accv[8];
#pragma unroll
    for (int t = 0; t < 8; t++) accv[t] = 0.f;
    for (int i = 0; i < CC; i++){
        float w = LW[i * 64 + o];
#pragma unroll
        for (int t = 0; t < 8; t++) accv[t] = fmaf(xt[rq * 8 + t][i], w, accv[t]);
    }
#pragma unroll
    for (int t = 0; t < 8; t++){
        size_t r = row0 + rq * 8 + t;
        int n = (int)(r & (NN - 1));
        float xs = g_scale[n] * accv[t] + lbs[o];
        float sg = 1.f / (1.f + __expf(-xs));
        out[r * 64 + o] = sg * xs;
    }
}

// ---------------- 8: gconv out += x@W0 + Y@W1 + bias ----------------
__global__ __launch_bounds__(256) void k_final(const float* __restrict__ x,
                                               const float* __restrict__ E,
                                               const float* __restrict__ bp,
                                               float* __restrict__ out){
    __shared__ float W[8192];
    __shared__ float4 Xs[16][16];
    __shared__ float4 Ys[16][16];
    __shared__ float bias_s[CC];
    __shared__ float e_s[DE];
    int n = blockIdx.x, tid = threadIdx.x;
    if (tid < DE) e_s[tid] = E[(size_t)n * DE + tid];
    __syncthreads();
    {
        const float4* src = (const float4*)(g_W + (size_t)n * 8192);
        for (int t = tid; t < 2048; t += 256) ((float4*)W)[t] = src[t];
    }
    if (tid < CC){
        float s = 0.f;
#pragma unroll
        for (int d = 0; d < DE; d++) s += e_s[d] * bp[d * 64 + tid];
        bias_s[tid] = s;
    }
    __syncthreads();
    int o = tid & 63, g = tid >> 6;
    for (int pass = 0; pass < 2; pass++){
        int bbase = pass * 16;
        __syncthreads();
        {
            int b = tid >> 4, i4 = tid & 15;
            Xs[b][i4] = *(const float4*)&x[((size_t)(bbase + b) * NN + n) * 64 + i4 * 4];
            Ys[b][i4] = *(const float4*)&g_Y[(size_t)n * NBJ + (bbase + b) * 64 + i4 * 4];
        }
        __syncthreads();
        float acc[4] = {0.f, 0.f, 0.f, 0.f};
#pragma unroll 4
        for (int i4 = 0; i4 < 16; i4++){
            int ib = i4 * 4;
            float w00 = W[(ib + 0) * 64 + o], w01 = W[(ib + 1) * 64 + o];
            float w02 = W[(ib + 2) * 64 + o], w03 = W[(ib + 3) * 64 + o];
            float w10 = W[4096 + (ib + 0) * 64 + o], w11 = W[4096 + (ib + 1) * 64 + o];
            float w12 = W[4096 + (ib + 2) * 64 + o], w13 = W[4096 + (ib + 3) * 64 + o];
#pragma unroll
            for (int t = 0; t < 4; t++){
                float4 xv = Xs[g + 4 * t][i4];
                float4 yv = Ys[g + 4 * t][i4];
                float a = acc[t];
                a = fmaf(xv.x, w00, a); a = fmaf(xv.y, w01, a);
                a = fmaf(xv.z, w02, a); a = fmaf(xv.w, w03, a);
                a = fmaf(yv.x, w10, a); a = fmaf(yv.y, w11, a);
                a = fmaf(yv.z, w12, a); a = fmaf(yv.w, w13, a);
                acc[t] = a;
            }
        }
#pragma unroll
        for (int t = 0; t < 4; t++){
            int b = bbase + g + 4 * t;
            size_t oi = ((size_t)b * NN + n) * 64 + o;
            out[oi] += acc[t] + bias_s[o];
        }
    }
}

// ---------------- launch ----------------
extern "C" void kernel_launch(void* const* d_in, const int* in_sizes, int n_in,
                              void* d_out, int out_size){
    const float* x   = (const float*)d_in[0];
    const float* E   = (const float*)d_in[1];
    const float* wp  = (const float*)d_in[2];
    const float* bp  = (const float*)d_in[3];
    const float* lw  = (const float*)d_in[4];
    const float* lb  = (const float*)d_in[5];
    const float* adj = (const float*)d_in[6];
    float* out = (float*)d_out;
    (void)in_sizes; (void)n_in; (void)out_size;

    cudaFuncSetAttribute(k_gemm_mma, cudaFuncAttributeMaxDynamicSharedMemorySize, GEMM_SMEM);

    k_zero    <<<16, 256>>>();
    k_rowsum  <<<NN, 256>>>(adj);
    k_scale   <<<NN / 16, 256>>>(adj);
    k_dyn     <<<NN / 2, 256>>>(E);
    k_xsplit  <<<BB * 64, 256>>>(x);
    k_wgen    <<<dim3(16, 32), 256>>>(E, wp);
    k_gemm_mma<<<dim3(NBJ / 128, NN / 128), 256, GEMM_SMEM>>>();
    k_static  <<<(BB * NN) / 32, 256>>>(x, lw, lb, out);
    k_final   <<<NN, 256>>>(x, E, bp, out);
}

// round 4
// speedup vs baseline: 2.3439x; 1.3307x over previous
#include <cuda_runtime.h>
#include <cuda_fp16.h>
#include <cstdint>

// ---------------- problem constants ----------------
#define NN    4096      // nodes
#define BB    32        // batch
#define CC    64        // channels in/out
#define DE    16        // embedding dim
#define NBJ   2048      // B*C  (columns of the big GEMM)

// ---------------- device scratch (no allocs allowed) ----------------
__device__ __align__(256) __half g_Ah[(size_t)NN * NN];    // hi(S) fp16, 32 MB
__device__ __align__(256) __half g_Al[(size_t)NN * NN];    // lo(S) fp16, 32 MB
__device__ __align__(256) __half g_B [(size_t)NBJ * NN];   // fp16(x^T) [j][k], 16 MB
__device__ __align__(256) float g_Y [(size_t)NN * NBJ];    // S @ XT, 32 MB
__device__ __align__(256) float g_W [(size_t)NN * 8192];   // per-node weights, 134 MB
__device__ float g_sd[NN];
__device__ float g_scale[NN];

// ---------------- PTX helpers (base ISA: ldmatrix / mma.sync / cp.async) ------
__device__ __forceinline__ uint32_t smem_u32(const void* p){
    uint32_t a;
    asm("{ .reg .u64 t; cvta.to.shared.u64 t, %1; cvt.u32.u64 %0, t; }" : "=r"(a) : "l"(p));
    return a;
}
#define LDSM_X4(R, addr) \
    asm volatile("ldmatrix.sync.aligned.m8n8.x4.shared.b16 {%0,%1,%2,%3}, [%4];" \
        : "=r"((R)[0]), "=r"((R)[1]), "=r"((R)[2]), "=r"((R)[3]) : "r"(addr))
#define MMA16816(D, A, B0, B1) \
    asm volatile("mma.sync.aligned.m16n8k16.row.col.f32.f16.f16.f32 " \
        "{%0,%1,%2,%3}, {%4,%5,%6,%7}, {%8,%9}, {%0,%1,%2,%3};" \
        : "+f"((D)[0]), "+f"((D)[1]), "+f"((D)[2]), "+f"((D)[3]) \
        : "r"((A)[0]), "r"((A)[1]), "r"((A)[2]), "r"((A)[3]), "r"(B0), "r"(B1))
#define CP_ASYNC16(dst, src) \
    asm volatile("cp.async.cg.shared.global [%0], [%1], 16;" :: "r"(dst), "l"(src) : "memory")
#define CP_COMMIT() asm volatile("cp.async.commit_group;" ::: "memory")

// ---------------- reductions ----------------
__device__ __forceinline__ float warpSum(float v){
#pragma unroll
    for (int o = 16; o; o >>= 1) v += __shfl_xor_sync(0xffffffffu, v, o);
    return v;
}
__device__ __forceinline__ float warpMax(float v){
#pragma unroll
    for (int o = 16; o; o >>= 1) v = fmaxf(v, __shfl_xor_sync(0xffffffffu, v, o));
    return v;
}
__device__ __forceinline__ float blockSum(float v, float* red){
    v = warpSum(v);
    int lane = threadIdx.x & 31, w = threadIdx.x >> 5;
    if (lane == 0) red[w] = v;
    __syncthreads();
    float r = 0.f;
#pragma unroll
    for (int i = 0; i < 8; i++) r += red[i];
    __syncthreads();
    return r;
}
__device__ __forceinline__ float blockMax(float v, float* red){
    v = warpMax(v);
    int lane = threadIdx.x & 31, w = threadIdx.x >> 5;
    if (lane == 0) red[w] = v;
    __syncthreads();
    float r = -3.0e38f;
#pragma unroll
    for (int i = 0; i < 8; i++) r = fmaxf(r, red[i]);
    __syncthreads();
    return r;
}

// ---------------- 0: zero scale accumulator ----------------
__global__ void k_zero(){
    int i = blockIdx.x * 256 + threadIdx.x;
    if (i < NN) g_scale[i] = 0.f;
}

// ---------------- 1: rowsums of (adj + 0.5 I) -> g_sd ----------------
__global__ __launch_bounds__(256) void k_rowsum(const float* __restrict__ adj){
    __shared__ float red[8];
    int n = blockIdx.x;
    const float* row = adj + (size_t)n * NN;
    float s = 0.f;
    for (int m = threadIdx.x; m < NN; m += 256) s += row[m];
    if (threadIdx.x == 0) s += 0.5f;
    s = blockSum(s, red);
    if (threadIdx.x == 0) g_sd[n] = rsqrtf(s);
}

// ---------------- 2: double row-softmax of sym-normed adj, column sums ----------------
__global__ __launch_bounds__(256) void k_scale(const float* __restrict__ adj){
    __shared__ float rowbuf[NN];
    __shared__ float acc[NN];
    __shared__ float red[8];
    int tid = threadIdx.x;
    for (int m = tid; m < NN; m += 256) acc[m] = 0.f;
    for (int r = 0; r < 16; r++){
        int n = blockIdx.x * 16 + r;
        const float* row = adj + (size_t)n * NN;
        float sdn = g_sd[n];
        float lmax = -3.0e38f;
        for (int m = tid; m < NN; m += 256){
            float w = row[m] + ((m == n) ? 0.5f : 0.f);
            float v = sdn * w * g_sd[m];
            rowbuf[m] = v;
            lmax = fmaxf(lmax, v);
        }
        float bm = blockMax(lmax, red);
        float ls = 0.f;
        for (int m = tid; m < NN; m += 256){
            float e = __expf(rowbuf[m] - bm);
            rowbuf[m] = e; ls += e;
        }
        float inv = 1.f / blockSum(ls, red);
        float ls2 = 0.f;
        for (int m = tid; m < NN; m += 256){
            float e2 = __expf(fmaf(rowbuf[m], inv, -inv));
            rowbuf[m] = e2; ls2 += e2;
        }
        float inv2 = 1.f / blockSum(ls2, red);
        for (int m = tid; m < NN; m += 256) acc[m] += rowbuf[m] * inv2;
    }
    __syncthreads();
    for (int m = tid; m < NN; m += 256) atomicAdd(&g_scale[m], acc[m]);
}

// ---------------- 3: S = softmax(relu(E E^T)) -> fp16 hi/lo split ----------------
__global__ __launch_bounds__(256) void k_dyn(const float* __restrict__ E){
    __shared__ float rowbuf[2][NN];
    __shared__ float er[2][DE];
    __shared__ float red[8];
    int tid = threadIdx.x;
    int n0 = blockIdx.x * 2;
    if (tid < 2 * DE) er[tid / DE][tid % DE] = E[(n0 + tid / DE) * DE + (tid % DE)];
    __syncthreads();
    float lmax0 = 0.f, lmax1 = 0.f;
    for (int m = tid; m < NN; m += 256){
        const float4* ep = (const float4*)(E + (size_t)m * DE);
        float4 e0 = ep[0], e1 = ep[1], e2 = ep[2], e3 = ep[3];
        float em[16] = { e0.x,e0.y,e0.z,e0.w, e1.x,e1.y,e1.z,e1.w,
                         e2.x,e2.y,e2.z,e2.w, e3.x,e3.y,e3.z,e3.w };
        float d0 = 0.f, d1 = 0.f;
#pragma unroll
        for (int d = 0; d < DE; d++){ d0 += em[d] * er[0][d]; d1 += em[d] * er[1][d]; }
        float v0 = fmaxf(d0, 0.f), v1 = fmaxf(d1, 0.f);
        rowbuf[0][m] = v0; rowbuf[1][m] = v1;
        lmax0 = fmaxf(lmax0, v0); lmax1 = fmaxf(lmax1, v1);
    }
#pragma unroll
    for (int r = 0; r < 2; r++){
        float bm = blockMax(r == 0 ? lmax0 : lmax1, red);
        float ls = 0.f;
        for (int m = tid; m < NN; m += 256){
            float e = __expf(rowbuf[r][m] - bm);
            rowbuf[r][m] = e; ls += e;
        }
        float inv = 1.f / blockSum(ls, red);
        __half* oh = g_Ah + (size_t)(n0 + r) * NN;
        __half* ol = g_Al + (size_t)(n0 + r) * NN;
        for (int m = tid; m < NN; m += 256){
            float v = rowbuf[r][m] * inv;
            __half h = __float2half(v);
            oh[m] = h;
            ol[m] = __float2half(v - __half2float(h));
        }
    }
}

// ---------------- 4: x [B,N,C] -> B-operand [j=b*64+c][k] fp16 ----------------
__global__ __launch_bounds__(256) void k_xsplit(const float* __restrict__ x){
    __shared__ float xs[64][65];
    int b  = blockIdx.x >> 6;
    int kc = blockIdx.x & 63;
    int tid = threadIdx.x;
    const float* src = x + ((size_t)b * NN + kc * 64) * 64;
    for (int t = tid; t < 1024; t += 256){
        int kk = t >> 4, c4 = t & 15;
        float4 v = ((const float4*)src)[(size_t)kk * 16 + c4];
        xs[kk][c4 * 4 + 0] = v.x; xs[kk][c4 * 4 + 1] = v.y;
        xs[kk][c4 * 4 + 2] = v.z; xs[kk][c4 * 4 + 3] = v.w;
    }
    __syncthreads();
    int c = tid >> 2, q = tid & 3;
    union { __half h[16]; uint4 u[2]; } uh;
#pragma unroll
    for (int i = 0; i < 16; i++)
        uh.h[i] = __float2half(xs[q * 16 + i][c]);
    size_t off = ((size_t)(b * 64 + c)) * NN + kc * 64 + q * 16;
    *(uint4*)(g_B + off) = uh.u[0]; *(uint4*)(g_B + off + 8) = uh.u[1];
}

// ---------------- 5: per-node weights ----------------
__global__ __launch_bounds__(256) void k_wgen(const float* __restrict__ E,
                                              const float* __restrict__ wp){
    __shared__ float wpc[DE * 512];
    __shared__ float es[128 * DE];
    int tid = threadIdx.x;
    int c0 = blockIdx.x * 512;
    int n0 = blockIdx.y * 128;
    for (int t = tid; t < DE * 512; t += 256){
        int d = t >> 9, j = t & 511;
        wpc[t] = wp[(size_t)d * 8192 + c0 + j];
    }
    for (int t = tid; t < 128 * DE; t += 256) es[t] = E[(size_t)n0 * DE + t];
    __syncthreads();
    for (int t = tid; t < 128 * 512; t += 256){
        int nl = t >> 9, j = t & 511;
        float s = 0.f;
#pragma unroll
        for (int d = 0; d < DE; d++) s += es[nl * DE + d] * wpc[d * 512 + j];
        g_W[(size_t)(n0 + nl) * 8192 + c0 + j] = s;
    }
}

// ---------------- 6: HMMA GEMM  Y = S @ XT  (fp16 hi/lo 2-product) ----------
// Block 128x128, warp tile 32x64 (4x2 warps), K-chunk 32, 3-stage cp.async.
// 3 tiles/stage (Ah, Al, B), rows padded to 80B -> ldmatrix conflict-free.
#define TILE_BYTES  10240
#define STAGE_BYTES (3 * TILE_BYTES)
#define GEMM_SMEM   (3 * STAGE_BYTES)

__global__ __launch_bounds__(256, 2) void k_gemm_mma(){
    extern __shared__ __align__(1024) char smem[];
    uint32_t sm = smem_u32(smem);
    int tid = threadIdx.x, wid = tid >> 5, lane = tid & 31;
    int bx = blockIdx.x, by = blockIdx.y;

    const char* pAh = (const char*)g_Ah + (size_t)(by * 128) * (NN * 2);
    const char* pAl = (const char*)g_Al + (size_t)(by * 128) * (NN * 2);
    const char* pB  = (const char*)g_B  + (size_t)(bx * 128) * (NN * 2);

    int m0 = (wid & 3) * 32;
    int n0 = (wid >> 2) * 64;

    uint32_t a_off = (uint32_t)((m0 + (lane & 15)) * 80 + ((lane >> 4) << 4));
    uint32_t b_off = (uint32_t)((n0 + ((lane >> 4) << 3) + (lane & 7)) * 80
                                + (((lane >> 3) & 1) << 4));

    auto load_stage = [&](int buf, int kblk){
        uint32_t sbase = sm + (uint32_t)buf * STAGE_BYTES;
        size_t kb = (size_t)kblk * 64;             // 32 fp16 = 64B per row chunk
#pragma unroll
        for (int i = 0; i < 6; i++){
            int id = tid + i * 256;                // 0..1535
            int tile = id >> 9;                    // 0..2: Ah, Al, B
            int r = (id >> 2) & 127;
            int c = id & 3;
            const char* gb = (tile == 0) ? pAh : (tile == 1) ? pAl : pB;
            const char* src = gb + (size_t)r * (NN * 2) + kb + (size_t)c * 16;
            uint32_t dst = sbase + (uint32_t)tile * TILE_BYTES + (uint32_t)(r * 80 + c * 16);
            CP_ASYNC16(dst, src);
        }
        CP_COMMIT();
    };

    float acc[2][8][4];
#pragma unroll
    for (int tm = 0; tm < 2; tm++)
#pragma unroll
        for (int nb = 0; nb < 8; nb++)
#pragma unroll
            for (int q = 0; q < 4; q++) acc[tm][nb][q] = 0.f;

    load_stage(0, 0);
    load_stage(1, 1);

    const int NIT = NN / 32;          // 128 iterations
    for (int s = 0; s < NIT; s++){
        if (s + 2 < NIT) asm volatile("cp.async.wait_group 1;" ::: "memory");
        else             asm volatile("cp.async.wait_group 0;" ::: "memory");
        __syncthreads();
        if (s + 2 < NIT) load_stage((s + 2) % 3, s + 2);

        uint32_t st = sm + (uint32_t)(s % 3) * STAGE_BYTES;
        uint32_t aAh = st + a_off;
        uint32_t aAl = st + TILE_BYTES + a_off;
        uint32_t aB  = st + 2 * TILE_BYTES + b_off;
#pragma unroll
        for (int ks = 0; ks < 2; ks++){
            uint32_t ko = (uint32_t)(ks * 32);
            uint32_t Ahf[2][4], Alf[2][4], Bf[4][4];
            LDSM_X4(Ahf[0], aAh + ko);
            LDSM_X4(Ahf[1], aAh + 1280 + ko);       // +16 rows * 80B
            LDSM_X4(Alf[0], aAl + ko);
            LDSM_X4(Alf[1], aAl + 1280 + ko);
#pragma unroll
            for (int p = 0; p < 4; p++)
                LDSM_X4(Bf[p], aB + (uint32_t)(p * 1280) + ko);
#pragma unroll
            for (int tm = 0; tm < 2; tm++)
#pragma unroll
                for (int nb = 0; nb < 8; nb++){
                    int p = nb >> 1, h = (nb & 1) * 2;
                    MMA16816(acc[tm][nb], Ahf[tm], Bf[p][h], Bf[p][h + 1]);
                    MMA16816(acc[tm][nb], Alf[tm], Bf[p][h], Bf[p][h + 1]);
                }
        }
    }

    int gr = lane >> 2, gc = (lane & 3) * 2;
#pragma unroll
    for (int tm = 0; tm < 2; tm++){
        int row = by * 128 + m0 + tm * 16 + gr;
        float* y0 = g_Y + (size_t)row * NBJ + bx * 128 + n0 + gc;
        float* y1 = y0 + 8 * NBJ;
#pragma unroll
        for (int nb = 0; nb < 8; nb++){
            *(float2*)(y0 + nb * 8) = make_float2(acc[tm][nb][0], acc[tm][nb][1]);
            *(float2*)(y1 + nb * 8) = make_float2(acc[tm][nb][2], acc[tm][nb][3]);
        }
    }
}

// ---------------- 7: static branch ----------------
__global__ __launch_bounds__(256) void k_static(const float* __restrict__ x,
                                                const float* __restrict__ lw,
                                                const float* __restrict__ lb,
                                                float* __restrict__ out){
    __shared__ float LW[CC * CC];
    __shared__ float xt[32][CC];
    __shared__ float lbs[CC];
    int tid = threadIdx.x;
    for (int idx = tid; idx < CC * CC; idx += 256){
        int o = idx & 63, i = idx >> 6;
        LW[i * 64 + o] = lw[o * 64 + i];
    }
    if (tid < CC) lbs[tid] = lb[tid];
    size_t row0 = (size_t)blockIdx.x * 32;
    for (int idx = tid; idx < 512; idx += 256){
        int r = idx >> 4, i4 = idx & 15;
        ((float4*)&xt[r][0])[i4] = *(const float4*)&x[(row0 + r) * 64 + i4 * 4];
    }
    __syncthreads();
    int o = tid & 63, rq = tid >> 6;
    float accv[8];
#pragma unroll
    for (int t = 0; t < 8; t++) accv[t] = 0.f;
    for (int i = 0; i < CC; i++){
        float w = LW[i * 64 + o];
#pragma unroll
        for (int t = 0; t < 8; t++) accv[t] = fmaf(xt[rq * 8 + t][i], w, accv[t]);
    }
#pragma unroll
    for (int t = 0; t < 8; t++){
        size_t r = row0 + rq * 8 + t;
        int n = (int)(r & (NN - 1));
        float xs = g_scale[n] * accv[t] + lbs[o];
        float sg = 1.f / (1.f + __expf(-xs));
        out[r * 64 + o] = sg * xs;
    }
}

// ---------------- 8: gconv out += x@W0 + Y@W1 + bias ----------------
__global__ __launch_bounds__(256) void k_final(const float* __restrict__ x,
                                               const float* __restrict__ E,
                                               const float* __restrict__ bp,
                                               float* __restrict__ out){
    __shared__ float W[8192];
    __shared__ float4 Xs[16][16];
    __shared__ float4 Ys[16][16];
    __shared__ float bias_s[CC];
    __shared__ float e_s[DE];
    int n = blockIdx.x, tid = threadIdx.x;
    if (tid < DE) e_s[tid] = E[(size_t)n * DE + tid];
    __syncthreads();
    {
        const float4* src = (const float4*)(g_W + (size_t)n * 8192);
        for (int t = tid; t < 2048; t += 256) ((float4*)W)[t] = src[t];
    }
    if (tid < CC){
        float s = 0.f;
#pragma unroll
        for (int d = 0; d < DE; d++) s += e_s[d] * bp[d * 64 + tid];
        bias_s[tid] = s;
    }
    __syncthreads();
    int o = tid & 63, g = tid >> 6;
    for (int pass = 0; pass < 2; pass++){
        int bbase = pass * 16;
        __syncthreads();
        {
            int b = tid >> 4, i4 = tid & 15;
            Xs[b][i4] = *(const float4*)&x[((size_t)(bbase + b) * NN + n) * 64 + i4 * 4];
            Ys[b][i4] = *(const float4*)&g_Y[(size_t)n * NBJ + (bbase + b) * 64 + i4 * 4];
        }
        __syncthreads();
        float acc[4] = {0.f, 0.f, 0.f, 0.f};
#pragma unroll 4
        for (int i4 = 0; i4 < 16; i4++){
            int ib = i4 * 4;
            float w00 = W[(ib + 0) * 64 + o], w01 = W[(ib + 1) * 64 + o];
            float w02 = W[(ib + 2) * 64 + o], w03 = W[(ib + 3) * 64 + o];
            float w10 = W[4096 + (ib + 0) * 64 + o], w11 = W[4096 + (ib + 1) * 64 + o];
            float w12 = W[4096 + (ib + 2) * 64 + o], w13 = W[4096 + (ib + 3) * 64 + o];
#pragma unroll
            for (int t = 0; t < 4; t++){
                float4 xv = Xs[g + 4 * t][i4];
                float4 yv = Ys[g + 4 * t][i4];
                float a = acc[t];
                a = fmaf(xv.x, w00, a); a = fmaf(xv.y, w01, a);
                a = fmaf(xv.z, w02, a); a = fmaf(xv.w, w03, a);
                a = fmaf(yv.x, w10, a); a = fmaf(yv.y, w11, a);
                a = fmaf(yv.z, w12, a); a = fmaf(yv.w, w13, a);
                acc[t] = a;
            }
        }
#pragma unroll
        for (int t = 0; t < 4; t++){
            int b = bbase + g + 4 * t;
            size_t oi = ((size_t)b * NN + n) * 64 + o;
            out[oi] += acc[t] + bias_s[o];
        }
    }
}

// ---------------- launch ----------------
extern "C" void kernel_launch(void* const* d_in, const int* in_sizes, int n_in,
                              void* d_out, int out_size){
    const float* x   = (const float*)d_in[0];
    const float* E   = (const float*)d_in[1];
    const float* wp  = (const float*)d_in[2];
    const float* bp  = (const float*)d_in[3];
    const float* lw  = (const float*)d_in[4];
    const float* lb  = (const float*)d_in[5];
    const float* adj = (const float*)d_in[6];
    float* out = (float*)d_out;
    (void)in_sizes; (void)n_in; (void)out_size;

    cudaFuncSetAttribute(k_gemm_mma, cudaFuncAttributeMaxDynamicSharedMemorySize, GEMM_SMEM);

    k_zero    <<<16, 256>>>();
    k_rowsum  <<<NN, 256>>>(adj);
    k_scale   <<<NN / 16, 256>>>(adj);
    k_dyn     <<<NN / 2, 256>>>(E);
    k_xsplit  <<<BB * 64, 256>>>(x);
    k_wgen    <<<dim3(16, 32), 256>>>(E, wp);
    k_gemm_mma<<<dim3(NBJ / 128, NN / 128), 256, GEMM_SMEM>>>();
    k_static  <<<(BB * NN) / 32, 256>>>(x, lw, lb, out);
    k_final   <<<NN, 256>>>(x, E, bp, out);
}

// round 6
// speedup vs baseline: 2.7836x; 1.1876x over previous
#include <cuda_runtime.h>
#include <cuda_fp16.h>
#include <cstdint>

// ---------------- problem constants ----------------
#define NN    4096      // nodes
#define BB    32        // batch
#define CC    64        // channels in/out
#define DE    16        // embedding dim
#define NBJ   2048      // B*C  (columns of the big GEMM)

// ---------------- device scratch (no allocs allowed) ----------------
__device__ __align__(256) __half g_Ah[(size_t)NN * NN];    // hi(S) fp16, 32 MB
__device__ __align__(256) __half g_Al[(size_t)NN * NN];    // lo(S) fp16, 32 MB
__device__ __align__(256) __half g_B [(size_t)NBJ * NN];   // fp16(x^T) [j][k], 16 MB
__device__ __align__(256) float  g_Y [(size_t)NN * NBJ];   // S @ XT, 32 MB
__device__ __align__(256) __half g_W16[(size_t)NN * 8192]; // per-node weights fp16, 67 MB
__device__ float g_sd[NN];
__device__ float g_scale[NN];

// ---------------- fast exp: 6-FFMA exp2 poly + exponent bit trick -------------
__device__ __forceinline__ float fast_exp(float x){
    float t = fminf(fmaxf(x * 1.4426950408889634f, -125.f), 125.f);
    float fi = floorf(t);
    float f = t - fi;
    float p =            1.3393720e-3f;
    p = fmaf(p, f, 9.6181291e-3f);
    p = fmaf(p, f, 5.5504109e-2f);
    p = fmaf(p, f, 2.4022651e-1f);
    p = fmaf(p, f, 6.9314718e-1f);
    p = fmaf(p, f, 1.0f);
    return __int_as_float(__float_as_int(p) + ((int)fi << 23));
}

// ---------------- PTX helpers (base ISA: ldmatrix / mma.sync / cp.async) ------
__device__ __forceinline__ uint32_t smem_u32(const void* p){
    uint32_t a;
    asm("{ .reg .u64 t; cvta.to.shared.u64 t, %1; cvt.u32.u64 %0, t; }" : "=r"(a) : "l"(p));
    return a;
}
#define LDSM_X4(R, addr) \
    asm volatile("ldmatrix.sync.aligned.m8n8.x4.shared.b16 {%0,%1,%2,%3}, [%4];" \
        : "=r"((R)[0]), "=r"((R)[1]), "=r"((R)[2]), "=r"((R)[3]) : "r"(addr))
#define MMA16816(D, A, B0, B1) \
    asm volatile("mma.sync.aligned.m16n8k16.row.col.f32.f16.f16.f32 " \
        "{%0,%1,%2,%3}, {%4,%5,%6,%7}, {%8,%9}, {%0,%1,%2,%3};" \
        : "+f"((D)[0]), "+f"((D)[1]), "+f"((D)[2]), "+f"((D)[3]) \
        : "r"((A)[0]), "r"((A)[1]), "r"((A)[2]), "r"((A)[3]), "r"(B0), "r"(B1))
#define CP_ASYNC16(dst, src) \
    asm volatile("cp.async.cg.shared.global [%0], [%1], 16;" :: "r"(dst), "l"(src) : "memory")
#define CP_COMMIT() asm volatile("cp.async.commit_group;" ::: "memory")

// ---------------- reductions ----------------
__device__ __forceinline__ float warpSum(float v){
#pragma unroll
    for (int o = 16; o; o >>= 1) v += __shfl_xor_sync(0xffffffffu, v, o);
    return v;
}
__device__ __forceinline__ float blockSum(float v, float* red){
    v = warpSum(v);
    int lane = threadIdx.x & 31, w = threadIdx.x >> 5;
    if (lane == 0) red[w] = v;
    __syncthreads();
    float r = 0.f;
#pragma unroll
    for (int i = 0; i < 8; i++) r += red[i];
    __syncthreads();
    return r;
}

// ---------------- 0: zero scale accumulator ----------------
__global__ void k_zero(){
    int i = blockIdx.x * 256 + threadIdx.x;
    if (i < NN) g_scale[i] = 0.f;
}

// ---------------- 1: rowsums of (adj + 0.5 I) -> g_sd ----------------
__global__ __launch_bounds__(256) void k_rowsum(const float* __restrict__ adj){
    __shared__ float red[8];
    int n = blockIdx.x;
    const float* row = adj + (size_t)n * NN;
    float s = 0.f;
    for (int m = threadIdx.x; m < NN; m += 256) s += row[m];
    if (threadIdx.x == 0) s += 0.5f;
    s = blockSum(s, red);
    if (threadIdx.x == 0) g_sd[n] = rsqrtf(s);
}

// ---------------- 2: double row-softmax of sym-normed adj, column sums --------
// No max subtraction (logits tiny); poly exp; 3 smem passes per row.
__global__ __launch_bounds__(256) void k_scale(const float* __restrict__ adj){
    __shared__ float rowbuf[NN];
    __shared__ float acc[NN];
    __shared__ float red[8];
    int tid = threadIdx.x;
    for (int m = tid; m < NN; m += 256) acc[m] = 0.f;
    __syncthreads();
    for (int r = 0; r < 16; r++){
        int n = blockIdx.x * 16 + r;
        const float* row = adj + (size_t)n * NN;
        float sdn = g_sd[n];
        float ls = 0.f;
        for (int m = tid; m < NN; m += 256){
            float w = row[m] + ((m == n) ? 0.5f : 0.f);
            float e = fast_exp(sdn * w * g_sd[m]);
            rowbuf[m] = e; ls += e;
        }
        float inv = 1.f / blockSum(ls, red);
        float ls2 = 0.f;
        for (int m = tid; m < NN; m += 256){
            float e2 = fast_exp(rowbuf[m] * inv);
            rowbuf[m] = e2; ls2 += e2;
        }
        float inv2 = 1.f / blockSum(ls2, red);
        for (int m = tid; m < NN; m += 256) acc[m] += rowbuf[m] * inv2;
        __syncthreads();
    }
    for (int m = tid; m < NN; m += 256) atomicAdd(&g_scale[m], acc[m]);
}

// ---------------- 3: S = softmax(relu(E E^T)) -> fp16 hi/lo -------------------
// 4 rows/block (dynamic 64KB rowbuf); no max pass; poly exp.
#define DYN_ROWS 4
#define DYN_SMEM (DYN_ROWS * NN * 4)
__global__ __launch_bounds__(256) void k_dyn(const float* __restrict__ E){
    extern __shared__ float rb[];                 // [DYN_ROWS][NN]
    __shared__ float er[DYN_ROWS][DE];
    __shared__ float red[8];
    int tid = threadIdx.x;
    int n0 = blockIdx.x * DYN_ROWS;
    if (tid < DYN_ROWS * DE) er[tid / DE][tid % DE] = E[(n0 + tid / DE) * DE + (tid % DE)];
    __syncthreads();
    float ls[DYN_ROWS] = {0.f, 0.f, 0.f, 0.f};
    for (int m = tid; m < NN; m += 256){
        const float4* ep = (const float4*)(E + (size_t)m * DE);
        float4 e0 = ep[0], e1 = ep[1], e2 = ep[2], e3 = ep[3];
        float em[16] = { e0.x,e0.y,e0.z,e0.w, e1.x,e1.y,e1.z,e1.w,
                         e2.x,e2.y,e2.z,e2.w, e3.x,e3.y,e3.z,e3.w };
#pragma unroll
        for (int r = 0; r < DYN_ROWS; r++){
            float d = 0.f;
#pragma unroll
            for (int k = 0; k < DE; k++) d += em[k] * er[r][k];
            float e = fast_exp(fmaxf(d, 0.f));
            rb[r * NN + m] = e;
            ls[r] += e;
        }
    }
    float inv[DYN_ROWS];
#pragma unroll
    for (int r = 0; r < DYN_ROWS; r++) inv[r] = 1.f / blockSum(ls[r], red);
#pragma unroll
    for (int r = 0; r < DYN_ROWS; r++){
        __half* oh = g_Ah + (size_t)(n0 + r) * NN;
        __half* ol = g_Al + (size_t)(n0 + r) * NN;
        for (int m = tid; m < NN; m += 256){
            float v = rb[r * NN + m] * inv[r];
            __half h = __float2half(v);
            oh[m] = h;
            ol[m] = __float2half(v - __half2float(h));
        }
    }
}

// ---------------- 4: x [B,N,C] -> B-operand [j=b*64+c][k] fp16 ----------------
__global__ __launch_bounds__(256) void k_xsplit(const float* __restrict__ x){
    __shared__ float xs[64][65];
    int b  = blockIdx.x >> 6;
    int kc = blockIdx.x & 63;
    int tid = threadIdx.x;
    const float* src = x + ((size_t)b * NN + kc * 64) * 64;
    for (int t = tid; t < 1024; t += 256){
        int kk = t >> 4, c4 = t & 15;
        float4 v = ((const float4*)src)[(size_t)kk * 16 + c4];
        xs[kk][c4 * 4 + 0] = v.x; xs[kk][c4 * 4 + 1] = v.y;
        xs[kk][c4 * 4 + 2] = v.z; xs[kk][c4 * 4 + 3] = v.w;
    }
    __syncthreads();
    int c = tid >> 2, q = tid & 3;
    union { __half h[16]; uint4 u[2]; } uh;
#pragma unroll
    for (int i = 0; i < 16; i++)
        uh.h[i] = __float2half(xs[q * 16 + i][c]);
    size_t off = ((size_t)(b * 64 + c)) * NN + kc * 64 + q * 16;
    *(uint4*)(g_B + off) = uh.u[0]; *(uint4*)(g_B + off + 8) = uh.u[1];
}

// ---------------- 5: per-node weights -> fp16 ---------------------------------
__global__ __launch_bounds__(256) void k_wgen(const float* __restrict__ E,
                                              const float* __restrict__ wp){
    __shared__ float wpc[DE * 512];
    __shared__ float es[128 * DE];
    int tid = threadIdx.x;
    int c0 = blockIdx.x * 512;
    int n0 = blockIdx.y * 128;
    for (int t = tid; t < DE * 512; t += 256){
        int d = t >> 9, j = t & 511;
        wpc[t] = wp[(size_t)d * 8192 + c0 + j];
    }
    for (int t = tid; t < 128 * DE; t += 256) es[t] = E[(size_t)n0 * DE + t];
    __syncthreads();
    for (int t = tid; t < 128 * 256; t += 256){   // each t does 2 adjacent j
        int nl = t >> 8, j2 = (t & 255) * 2;
        float s0 = 0.f, s1 = 0.f;
#pragma unroll
        for (int d = 0; d < DE; d++){
            float e = es[nl * DE + d];
            s0 += e * wpc[d * 512 + j2];
            s1 += e * wpc[d * 512 + j2 + 1];
        }
        *(__half2*)&g_W16[(size_t)(n0 + nl) * 8192 + c0 + j2] =
            __floats2half2_rn(s0, s1);
    }
}

// ---------------- 6: HMMA GEMM  Y = S @ XT  (fp16 hi/lo 2-product) ------------
#define TILE_BYTES  10240
#define STAGE_BYTES (3 * TILE_BYTES)
#define GEMM_SMEM   (3 * STAGE_BYTES)

__global__ __launch_bounds__(256, 2) void k_gemm_mma(){
    extern __shared__ __align__(1024) char smem[];
    uint32_t sm = smem_u32(smem);
    int tid = threadIdx.x, wid = tid >> 5, lane = tid & 31;
    int bx = blockIdx.x, by = blockIdx.y;

    const char* pAh = (const char*)g_Ah + (size_t)(by * 128) * (NN * 2);
    const char* pAl = (const char*)g_Al + (size_t)(by * 128) * (NN * 2);
    const char* pB  = (const char*)g_B  + (size_t)(bx * 128) * (NN * 2);

    int m0 = (wid & 3) * 32;
    int n0 = (wid >> 2) * 64;

    uint32_t a_off = (uint32_t)((m0 + (lane & 15)) * 80 + ((lane >> 4) << 4));
    uint32_t b_off = (uint32_t)((n0 + ((lane >> 4) << 3) + (lane & 7)) * 80
                                + (((lane >> 3) & 1) << 4));

    auto load_stage = [&](int buf, int kblk){
        uint32_t sbase = sm + (uint32_t)buf * STAGE_BYTES;
        size_t kb = (size_t)kblk * 64;
#pragma unroll
        for (int i = 0; i < 6; i++){
            int id = tid + i * 256;
            int tile = id >> 9;
            int r = (id >> 2) & 127;
            int c = id & 3;
            const char* gb = (tile == 0) ? pAh : (tile == 1) ? pAl : pB;
            const char* src = gb + (size_t)r * (NN * 2) + kb + (size_t)c * 16;
            uint32_t dst = sbase + (uint32_t)tile * TILE_BYTES + (uint32_t)(r * 80 + c * 16);
            CP_ASYNC16(dst, src);
        }
        CP_COMMIT();
    };

    float acc[2][8][4];
#pragma unroll
    for (int tm = 0; tm < 2; tm++)
#pragma unroll
        for (int nb = 0; nb < 8; nb++)
#pragma unroll
            for (int q = 0; q < 4; q++) acc[tm][nb][q] = 0.f;

    load_stage(0, 0);
    load_stage(1, 1);

    const int NIT = NN / 32;
    for (int s = 0; s < NIT; s++){
        if (s + 2 < NIT) asm volatile("cp.async.wait_group 1;" ::: "memory");
        else             asm volatile("cp.async.wait_group 0;" ::: "memory");
        __syncthreads();
        if (s + 2 < NIT) load_stage((s + 2) % 3, s + 2);

        uint32_t st = sm + (uint32_t)(s % 3) * STAGE_BYTES;
        uint32_t aAh = st + a_off;
        uint32_t aAl = st + TILE_BYTES + a_off;
        uint32_t aB  = st + 2 * TILE_BYTES + b_off;
#pragma unroll
        for (int ks = 0; ks < 2; ks++){
            uint32_t ko = (uint32_t)(ks * 32);
            uint32_t Ahf[2][4], Alf[2][4], Bf[4][4];
            LDSM_X4(Ahf[0], aAh + ko);
            LDSM_X4(Ahf[1], aAh + 1280 + ko);
            LDSM_X4(Alf[0], aAl + ko);
            LDSM_X4(Alf[1], aAl + 1280 + ko);
#pragma unroll
            for (int p = 0; p < 4; p++)
                LDSM_X4(Bf[p], aB + (uint32_t)(p * 1280) + ko);
#pragma unroll
            for (int tm = 0; tm < 2; tm++)
#pragma unroll
                for (int nb = 0; nb < 8; nb++){
                    int p = nb >> 1, h = (nb & 1) * 2;
                    MMA16816(acc[tm][nb], Ahf[tm], Bf[p][h], Bf[p][h + 1]);
                    MMA16816(acc[tm][nb], Alf[tm], Bf[p][h], Bf[p][h + 1]);
                }
        }
    }

    int gr = lane >> 2, gc = (lane & 3) * 2;
#pragma unroll
    for (int tm = 0; tm < 2; tm++){
        int row = by * 128 + m0 + tm * 16 + gr;
        float* y0 = g_Y + (size_t)row * NBJ + bx * 128 + n0 + gc;
        float* y1 = y0 + 8 * NBJ;
#pragma unroll
        for (int nb = 0; nb < 8; nb++){
            *(float2*)(y0 + nb * 8) = make_float2(acc[tm][nb][0], acc[tm][nb][1]);
            *(float2*)(y1 + nb * 8) = make_float2(acc[tm][nb][2], acc[tm][nb][3]);
        }
    }
}

// ---------------- 7: fused gconv + static branch ------------------------------
// out = (x@W0 + Y@W1 + bias) + sigmoid(xs)*xs,  xs = scale[n]*(x@lw^T) + lb
// One block per node. Dynamic smem layout:
//   W (fp32, 32KB) | LW (16KB) | Xs (4KB) | Ys (4KB)
#define FIN_W   0
#define FIN_LW  8192
#define FIN_XS  (FIN_LW + 4096)
#define FIN_YS  (FIN_XS + 1024)
#define FIN_SMEM ((FIN_YS + 1024) * 4)
__global__ __launch_bounds__(256) void k_final(const float* __restrict__ x,
                                               const float* __restrict__ E,
                                               const float* __restrict__ bp,
                                               const float* __restrict__ lw,
                                               const float* __restrict__ lb,
                                               float* __restrict__ out){
    extern __shared__ float sf[];
    float* W  = sf + FIN_W;
    float* LW = sf + FIN_LW;
    float4* Xs = (float4*)(sf + FIN_XS);          // [16][16]
    float4* Ys = (float4*)(sf + FIN_YS);
    __shared__ float bias_s[CC];
    __shared__ float lbs[CC];
    __shared__ float e_s[DE];
    int n = blockIdx.x, tid = threadIdx.x;
    if (tid < DE) e_s[tid] = E[(size_t)n * DE + tid];
    if (tid < CC) lbs[tid] = lb[tid];
    // W row: fp16 -> fp32 smem (coalesced uint4 = 8 halves)
    {
        const uint4* src = (const uint4*)(g_W16 + (size_t)n * 8192);
        for (int t = tid; t < 1024; t += 256){
            uint4 u = src[t];
            __half2* hp = (__half2*)&u;
            float* dst = W + t * 8;
#pragma unroll
            for (int q = 0; q < 4; q++){
                float2 f = __half22float2(hp[q]);
                dst[q * 2] = f.x; dst[q * 2 + 1] = f.y;
            }
        }
    }
    // LW[i*64+o] = lw[o*64+i]
    for (int idx = tid; idx < CC * CC; idx += 256){
        int o = idx & 63, i = idx >> 6;
        LW[i * 64 + o] = lw[o * 64 + i];
    }
    __syncthreads();
    if (tid < CC){
        float s = 0.f;
#pragma unroll
        for (int d = 0; d < DE; d++) s += e_s[d] * bp[d * 64 + tid];
        bias_s[tid] = s;
    }
    float scale_n = g_scale[n];
    int o = tid & 63, g = tid >> 6;
    for (int pass = 0; pass < 2; pass++){
        int bbase = pass * 16;
        __syncthreads();
        {
            int b = tid >> 4, i4 = tid & 15;
            Xs[b * 16 + i4] = *(const float4*)&x[((size_t)(bbase + b) * NN + n) * 64 + i4 * 4];
            Ys[b * 16 + i4] = *(const float4*)&g_Y[(size_t)n * NBJ + (bbase + b) * 64 + i4 * 4];
        }
        __syncthreads();
        float accg[4] = {0.f, 0.f, 0.f, 0.f};
        float accs[4] = {0.f, 0.f, 0.f, 0.f};
#pragma unroll 4
        for (int i4 = 0; i4 < 16; i4++){
            int ib = i4 * 4;
            float w00 = W[(ib + 0) * 64 + o], w01 = W[(ib + 1) * 64 + o];
            float w02 = W[(ib + 2) * 64 + o], w03 = W[(ib + 3) * 64 + o];
            float w10 = W[4096 + (ib + 0) * 64 + o], w11 = W[4096 + (ib + 1) * 64 + o];
            float w12 = W[4096 + (ib + 2) * 64 + o], w13 = W[4096 + (ib + 3) * 64 + o];
            float l0 = LW[(ib + 0) * 64 + o], l1 = LW[(ib + 1) * 64 + o];
            float l2 = LW[(ib + 2) * 64 + o], l3 = LW[(ib + 3) * 64 + o];
#pragma unroll
            for (int t = 0; t < 4; t++){
                float4 xv = Xs[(g + 4 * t) * 16 + i4];
                float4 yv = Ys[(g + 4 * t) * 16 + i4];
                float a = accg[t];
                a = fmaf(xv.x, w00, a); a = fmaf(xv.y, w01, a);
                a = fmaf(xv.z, w02, a); a = fmaf(xv.w, w03, a);
                a = fmaf(yv.x, w10, a); a = fmaf(yv.y, w11, a);
                a = fmaf(yv.z, w12, a); a = fmaf(yv.w, w13, a);
                accg[t] = a;
                float s = accs[t];
                s = fmaf(xv.x, l0, s); s = fmaf(xv.y, l1, s);
                s = fmaf(xv.z, l2, s); s = fmaf(xv.w, l3, s);
                accs[t] = s;
            }
        }
#pragma unroll
        for (int t = 0; t < 4; t++){
            int b = bbase + g + 4 * t;
            float xs = fmaf(scale_n, accs[t], lbs[o]);
            float sg = 1.f / (1.f + fast_exp(-xs));
            out[((size_t)b * NN + n) * 64 + o] = accg[t] + bias_s[o] + sg * xs;
        }
    }
}

// ---------------- launch ----------------
extern "C" void kernel_launch(void* const* d_in, const int* in_sizes, int n_in,
                              void* d_out, int out_size){
    const float* x   = (const float*)d_in[0];
    const float* E   = (const float*)d_in[1];
    const float* wp  = (const float*)d_in[2];
    const float* bp  = (const float*)d_in[3];
    const float* lw  = (const float*)d_in[4];
    const float* lb  = (const float*)d_in[5];
    const float* adj = (const float*)d_in[6];
    float* out = (float*)d_out;
    (void)in_sizes; (void)n_in; (void)out_size;

    cudaFuncSetAttribute(k_gemm_mma, cudaFuncAttributeMaxDynamicSharedMemorySize, GEMM_SMEM);
    cudaFuncSetAttribute(k_dyn,      cudaFuncAttributeMaxDynamicSharedMemorySize, DYN_SMEM);
    cudaFuncSetAttribute(k_final,    cudaFuncAttributeMaxDynamicSharedMemorySize, FIN_SMEM);

    k_zero    <<<16, 256>>>();
    k_rowsum  <<<NN, 256>>>(adj);
    k_scale   <<<NN / 16, 256>>>(adj);
    k_dyn     <<<NN / DYN_ROWS, 256, DYN_SMEM>>>(E);
    k_xsplit  <<<BB * 64, 256>>>(x);
    k_wgen    <<<dim3(16, 32), 256>>>(E, wp);
    k_gemm_mma<<<dim3(NBJ / 128, NN / 128), 256, GEMM_SMEM>>>();
    k_final   <<<NN, 256, FIN_SMEM>>>(x, E, bp, lw, lb, out);
}

// round 7
// speedup vs baseline: 3.5537x; 1.2767x over previous
#include <cuda_runtime.h>
#include <cuda_fp16.h>
#include <cstdint>

// ---------------- problem constants ----------------
#define NN    4096      // nodes
#define BB    32        // batch
#define CC    64        // channels in/out
#define DE    16        // embedding dim
#define NBJ   2048      // B*C  (columns of the big GEMM)

// ---------------- device scratch (no allocs allowed) ----------------
__device__ __align__(256) __half g_A [(size_t)NN * NN];    // fp16(S), 32 MB
__device__ __align__(256) __half g_B [(size_t)NBJ * NN];   // fp16(x^T) [j][k], 16 MB
__device__ __align__(256) float  g_Y [(size_t)NN * NBJ];   // S @ XT, 32 MB
__device__ __align__(256) __half g_W16[(size_t)NN * 8192]; // per-node weights fp16, 67 MB
__device__ float g_sd[NN];
__device__ float g_scale[NN];

// ---------------- fast exp: 6-FFMA exp2 poly + exponent bit trick -------------
__device__ __forceinline__ float fast_exp(float x){
    float t = fminf(fmaxf(x * 1.4426950408889634f, -125.f), 125.f);
    float fi = floorf(t);
    float f = t - fi;
    float p =            1.3393720e-3f;
    p = fmaf(p, f, 9.6181291e-3f);
    p = fmaf(p, f, 5.5504109e-2f);
    p = fmaf(p, f, 2.4022651e-1f);
    p = fmaf(p, f, 6.9314718e-1f);
    p = fmaf(p, f, 1.0f);
    return __int_as_float(__float_as_int(p) + ((int)fi << 23));
}

// ---------------- PTX helpers (base ISA: ldmatrix / mma.sync / cp.async) ------
__device__ __forceinline__ uint32_t smem_u32(const void* p){
    uint32_t a;
    asm("{ .reg .u64 t; cvta.to.shared.u64 t, %1; cvt.u32.u64 %0, t; }" : "=r"(a) : "l"(p));
    return a;
}
#define LDSM_X4(R, addr) \
    asm volatile("ldmatrix.sync.aligned.m8n8.x4.shared.b16 {%0,%1,%2,%3}, [%4];" \
        : "=r"((R)[0]), "=r"((R)[1]), "=r"((R)[2]), "=r"((R)[3]) : "r"(addr))
#define MMA16816(D, A, B0, B1) \
    asm volatile("mma.sync.aligned.m16n8k16.row.col.f32.f16.f16.f32 " \
        "{%0,%1,%2,%3}, {%4,%5,%6,%7}, {%8,%9}, {%0,%1,%2,%3};" \
        : "+f"((D)[0]), "+f"((D)[1]), "+f"((D)[2]), "+f"((D)[3]) \
        : "r"((A)[0]), "r"((A)[1]), "r"((A)[2]), "r"((A)[3]), "r"(B0), "r"(B1))
#define CP_ASYNC16(dst, src) \
    asm volatile("cp.async.cg.shared.global [%0], [%1], 16;" :: "r"(dst), "l"(src) : "memory")
#define CP_COMMIT() asm volatile("cp.async.commit_group;" ::: "memory")

// ---------------- reductions ----------------
__device__ __forceinline__ float warpSum(float v){
#pragma unroll
    for (int o = 16; o; o >>= 1) v += __shfl_xor_sync(0xffffffffu, v, o);
    return v;
}
__device__ __forceinline__ float blockSum(float v, float* red){
    v = warpSum(v);
    int lane = threadIdx.x & 31, w = threadIdx.x >> 5;
    if (lane == 0) red[w] = v;
    __syncthreads();
    float r = 0.f;
#pragma unroll
    for (int i = 0; i < 8; i++) r += red[i];
    __syncthreads();
    return r;
}

// ---------------- 0: zero scale accumulator ----------------
__global__ void k_zero(){
    int i = blockIdx.x * 256 + threadIdx.x;
    if (i < NN) g_scale[i] = 0.f;
}

// ---------------- 1: rowsums of (adj + 0.5 I) -> g_sd ----------------
__global__ __launch_bounds__(256) void k_rowsum(const float* __restrict__ adj){
    __shared__ float red[8];
    int n = blockIdx.x;
    const float* row = adj + (size_t)n * NN;
    float s = 0.f;
    for (int m = threadIdx.x; m < NN; m += 256) s += row[m];
    if (threadIdx.x == 0) s += 0.5f;
    s = blockSum(s, red);
    if (threadIdx.x == 0) g_sd[n] = rsqrtf(s);
}

// ---------------- 2: double row-softmax of sym-normed adj, column sums --------
__global__ __launch_bounds__(256) void k_scale(const float* __restrict__ adj){
    __shared__ float rowbuf[NN];
    __shared__ float acc[NN];
    __shared__ float red[8];
    int tid = threadIdx.x;
    for (int m = tid; m < NN; m += 256) acc[m] = 0.f;
    __syncthreads();
    for (int r = 0; r < 16; r++){
        int n = blockIdx.x * 16 + r;
        const float* row = adj + (size_t)n * NN;
        float sdn = g_sd[n];
        float ls = 0.f;
        for (int m = tid; m < NN; m += 256){
            float w = row[m] + ((m == n) ? 0.5f : 0.f);
            float e = fast_exp(sdn * w * g_sd[m]);
            rowbuf[m] = e; ls += e;
        }
        float inv = 1.f / blockSum(ls, red);
        float ls2 = 0.f;
        for (int m = tid; m < NN; m += 256){
            float e2 = fast_exp(rowbuf[m] * inv);
            rowbuf[m] = e2; ls2 += e2;
        }
        float inv2 = 1.f / blockSum(ls2, red);
        for (int m = tid; m < NN; m += 256) acc[m] += rowbuf[m] * inv2;
        __syncthreads();
    }
    for (int m = tid; m < NN; m += 256) atomicAdd(&g_scale[m], acc[m]);
}

// ---------------- 3: S = softmax(relu(E E^T)) -> fp16 -------------------------
#define DYN_ROWS 4
#define DYN_SMEM (DYN_ROWS * NN * 4)
__global__ __launch_bounds__(256) void k_dyn(const float* __restrict__ E){
    extern __shared__ float rb[];                 // [DYN_ROWS][NN]
    __shared__ float er[DYN_ROWS][DE];
    __shared__ float red[8];
    int tid = threadIdx.x;
    int n0 = blockIdx.x * DYN_ROWS;
    if (tid < DYN_ROWS * DE) er[tid / DE][tid % DE] = E[(n0 + tid / DE) * DE + (tid % DE)];
    __syncthreads();
    float ls[DYN_ROWS] = {0.f, 0.f, 0.f, 0.f};
    for (int m = tid; m < NN; m += 256){
        const float4* ep = (const float4*)(E + (size_t)m * DE);
        float4 e0 = ep[0], e1 = ep[1], e2 = ep[2], e3 = ep[3];
        float em[16] = { e0.x,e0.y,e0.z,e0.w, e1.x,e1.y,e1.z,e1.w,
                         e2.x,e2.y,e2.z,e2.w, e3.x,e3.y,e3.z,e3.w };
#pragma unroll
        for (int r = 0; r < DYN_ROWS; r++){
            float d = 0.f;
#pragma unroll
            for (int k = 0; k < DE; k++) d += em[k] * er[r][k];
            float e = fast_exp(fmaxf(d, 0.f));
            rb[r * NN + m] = e;
            ls[r] += e;
        }
    }
    float inv[DYN_ROWS];
#pragma unroll
    for (int r = 0; r < DYN_ROWS; r++) inv[r] = 1.f / blockSum(ls[r], red);
#pragma unroll
    for (int r = 0; r < DYN_ROWS; r++){
        __half* oh = g_A + (size_t)(n0 + r) * NN;
        for (int m = tid; m < NN; m += 256)
            oh[m] = __float2half(rb[r * NN + m] * inv[r]);
    }
}

// ---------------- 4: x [B,N,C] -> B-operand [j=b*64+c][k] fp16 ----------------
__global__ __launch_bounds__(256) void k_xsplit(const float* __restrict__ x){
    __shared__ float xs[64][65];
    int b  = blockIdx.x >> 6;
    int kc = blockIdx.x & 63;
    int tid = threadIdx.x;
    const float* src = x + ((size_t)b * NN + kc * 64) * 64;
    for (int t = tid; t < 1024; t += 256){
        int kk = t >> 4, c4 = t & 15;
        float4 v = ((const float4*)src)[(size_t)kk * 16 + c4];
        xs[kk][c4 * 4 + 0] = v.x; xs[kk][c4 * 4 + 1] = v.y;
        xs[kk][c4 * 4 + 2] = v.z; xs[kk][c4 * 4 + 3] = v.w;
    }
    __syncthreads();
    int c = tid >> 2, q = tid & 3;
    union { __half h[16]; uint4 u[2]; } uh;
#pragma unroll
    for (int i = 0; i < 16; i++)
        uh.h[i] = __float2half(xs[q * 16 + i][c]);
    size_t off = ((size_t)(b * 64 + c)) * NN + kc * 64 + q * 16;
    *(uint4*)(g_B + off) = uh.u[0]; *(uint4*)(g_B + off + 8) = uh.u[1];
}

// ---------------- 5: per-node weights -> fp16 ---------------------------------
__global__ __launch_bounds__(256) void k_wgen(const float* __restrict__ E,
                                              const float* __restrict__ wp){
    __shared__ float wpc[DE * 512];
    __shared__ float es[128 * DE];
    int tid = threadIdx.x;
    int c0 = blockIdx.x * 512;
    int n0 = blockIdx.y * 128;
    for (int t = tid; t < DE * 512; t += 256){
        int d = t >> 9, j = t & 511;
        wpc[t] = wp[(size_t)d * 8192 + c0 + j];
    }
    for (int t = tid; t < 128 * DE; t += 256) es[t] = E[(size_t)n0 * DE + t];
    __syncthreads();
    for (int t = tid; t < 128 * 256; t += 256){
        int nl = t >> 8, j2 = (t & 255) * 2;
        float s0 = 0.f, s1 = 0.f;
#pragma unroll
        for (int d = 0; d < DE; d++){
            float e = es[nl * DE + d];
            s0 += e * wpc[d * 512 + j2];
            s1 += e * wpc[d * 512 + j2 + 1];
        }
        *(__half2*)&g_W16[(size_t)(n0 + nl) * 8192 + c0 + j2] =
            __floats2half2_rn(s0, s1);
    }
}

// ---------------- 6: HMMA GEMM  Y = S @ XT  (single fp16 product) -------------
// Block 128x128, warp tile 32x64 (4x2 warps), K-chunk 32, 4-stage cp.async.
// 2 tiles/stage (A, B), rows padded to 80B -> ldmatrix conflict-free.
#define TILE_BYTES  10240
#define STAGE_BYTES (2 * TILE_BYTES)
#define GEMM_SMEM   (4 * STAGE_BYTES)

__global__ __launch_bounds__(256, 2) void k_gemm_mma(){
    extern __shared__ __align__(1024) char smem[];
    uint32_t sm = smem_u32(smem);
    int tid = threadIdx.x, wid = tid >> 5, lane = tid & 31;
    int bx = blockIdx.x, by = blockIdx.y;

    const char* pA = (const char*)g_A + (size_t)(by * 128) * (NN * 2);
    const char* pB = (const char*)g_B + (size_t)(bx * 128) * (NN * 2);

    int m0 = (wid & 3) * 32;
    int n0 = (wid >> 2) * 64;

    uint32_t a_off = (uint32_t)((m0 + (lane & 15)) * 80 + ((lane >> 4) << 4));
    uint32_t b_off = (uint32_t)((n0 + ((lane >> 4) << 3) + (lane & 7)) * 80
                                + (((lane >> 3) & 1) << 4));

    auto load_stage = [&](int buf, int kblk){
        uint32_t sbase = sm + (uint32_t)buf * STAGE_BYTES;
        size_t kb = (size_t)kblk * 64;             // 32 fp16 = 64B per row chunk
#pragma unroll
        for (int i = 0; i < 4; i++){
            int id = tid + i * 256;                // 0..1023
            int tile = id >> 9;                    // 0..1: A, B
            int r = (id >> 2) & 127;
            int c = id & 3;
            const char* gb = (tile == 0) ? pA : pB;
            const char* src = gb + (size_t)r * (NN * 2) + kb + (size_t)c * 16;
            uint32_t dst = sbase + (uint32_t)tile * TILE_BYTES + (uint32_t)(r * 80 + c * 16);
            CP_ASYNC16(dst, src);
        }
        CP_COMMIT();
    };

    float acc[2][8][4];
#pragma unroll
    for (int tm = 0; tm < 2; tm++)
#pragma unroll
        for (int nb = 0; nb < 8; nb++)
#pragma unroll
            for (int q = 0; q < 4; q++) acc[tm][nb][q] = 0.f;

    load_stage(0, 0);
    load_stage(1, 1);
    load_stage(2, 2);

    const int NIT = NN / 32;          // 128 iterations
    for (int s = 0; s < NIT; s++){
        if (s + 3 < NIT)      asm volatile("cp.async.wait_group 2;" ::: "memory");
        else if (s + 2 < NIT) asm volatile("cp.async.wait_group 1;" ::: "memory");
        else                  asm volatile("cp.async.wait_group 0;" ::: "memory");
        __syncthreads();
        if (s + 3 < NIT) load_stage((s + 3) & 3, s + 3);

        uint32_t st = sm + (uint32_t)(s & 3) * STAGE_BYTES;
        uint32_t aA = st + a_off;
        uint32_t aB = st + TILE_BYTES + b_off;
#pragma unroll
        for (int ks = 0; ks < 2; ks++){
            uint32_t ko = (uint32_t)(ks * 32);
            uint32_t Af[2][4], Bf[4][4];
            LDSM_X4(Af[0], aA + ko);
            LDSM_X4(Af[1], aA + 1280 + ko);         // +16 rows * 80B
#pragma unroll
            for (int p = 0; p < 4; p++)
                LDSM_X4(Bf[p], aB + (uint32_t)(p * 1280) + ko);
#pragma unroll
            for (int tm = 0; tm < 2; tm++)
#pragma unroll
                for (int nb = 0; nb < 8; nb++){
                    int p = nb >> 1, h = (nb & 1) * 2;
                    MMA16816(acc[tm][nb], Af[tm], Bf[p][h], Bf[p][h + 1]);
                }
        }
    }

    int gr = lane >> 2, gc = (lane & 3) * 2;
#pragma unroll
    for (int tm = 0; tm < 2; tm++){
        int row = by * 128 + m0 + tm * 16 + gr;
        float* y0 = g_Y + (size_t)row * NBJ + bx * 128 + n0 + gc;
        float* y1 = y0 + 8 * NBJ;
#pragma unroll
        for (int nb = 0; nb < 8; nb++){
            *(float2*)(y0 + nb * 8) = make_float2(acc[tm][nb][0], acc[tm][nb][1]);
            *(float2*)(y1 + nb * 8) = make_float2(acc[tm][nb][2], acc[tm][nb][3]);
        }
    }
}

// ---------------- 7: fused gconv + static branch ------------------------------
#define FIN_W   0
#define FIN_LW  8192
#define FIN_XS  (FIN_LW + 4096)
#define FIN_YS  (FIN_XS + 1024)
#define FIN_SMEM ((FIN_YS + 1024) * 4)
__global__ __launch_bounds__(256) void k_final(const float* __restrict__ x,
                                               const float* __restrict__ E,
                                               const float* __restrict__ bp,
                                               const float* __restrict__ lw,
                                               const float* __restrict__ lb,
                                               float* __restrict__ out){
    extern __shared__ float sf[];
    float* W  = sf + FIN_W;
    float* LW = sf + FIN_LW;
    float4* Xs = (float4*)(sf + FIN_XS);
    float4* Ys = (float4*)(sf + FIN_YS);
    __shared__ float bias_s[CC];
    __shared__ float lbs[CC];
    __shared__ float e_s[DE];
    int n = blockIdx.x, tid = threadIdx.x;
    if (tid < DE) e_s[tid] = E[(size_t)n * DE + tid];
    if (tid < CC) lbs[tid] = lb[tid];
    {
        const uint4* src = (const uint4*)(g_W16 + (size_t)n * 8192);
        for (int t = tid; t < 1024; t += 256){
            uint4 u = src[t];
            __half2* hp = (__half2*)&u;
            float* dst = W + t * 8;
#pragma unroll
            for (int q = 0; q < 4; q++){
                float2 f = __half22float2(hp[q]);
                dst[q * 2] = f.x; dst[q * 2 + 1] = f.y;
            }
        }
    }
    for (int idx = tid; idx < CC * CC; idx += 256){
        int o = idx & 63, i = idx >> 6;
        LW[i * 64 + o] = lw[o * 64 + i];
    }
    __syncthreads();
    if (tid < CC){
        float s = 0.f;
#pragma unroll
        for (int d = 0; d < DE; d++) s += e_s[d] * bp[d * 64 + tid];
        bias_s[tid] = s;
    }
    float scale_n = g_scale[n];
    int o = tid & 63, g = tid >> 6;
    for (int pass = 0; pass < 2; pass++){
        int bbase = pass * 16;
        __syncthreads();
        {
            int b = tid >> 4, i4 = tid & 15;
            Xs[b * 16 + i4] = *(const float4*)&x[((size_t)(bbase + b) * NN + n) * 64 + i4 * 4];
            Ys[b * 16 + i4] = *(const float4*)&g_Y[(size_t)n * NBJ + (bbase + b) * 64 + i4 * 4];
        }
        __syncthreads();
        float accg[4] = {0.f, 0.f, 0.f, 0.f};
        float accs[4] = {0.f, 0.f, 0.f, 0.f};
#pragma unroll 4
        for (int i4 = 0; i4 < 16; i4++){
            int ib = i4 * 4;
            float w00 = W[(ib + 0) * 64 + o], w01 = W[(ib + 1) * 64 + o];
            float w02 = W[(ib + 2) * 64 + o], w03 = W[(ib + 3) * 64 + o];
            float w10 = W[4096 + (ib + 0) * 64 + o], w11 = W[4096 + (ib + 1) * 64 + o];
            float w12 = W[4096 + (ib + 2) * 64 + o], w13 = W[4096 + (ib + 3) * 64 + o];
            float l0 = LW[(ib + 0) * 64 + o], l1 = LW[(ib + 1) * 64 + o];
            float l2 = LW[(ib + 2) * 64 + o], l3 = LW[(ib + 3) * 64 + o];
#pragma unroll
            for (int t = 0; t < 4; t++){
                float4 xv = Xs[(g + 4 * t) * 16 + i4];
                float4 yv = Ys[(g + 4 * t) * 16 + i4];
                float a = accg[t];
                a = fmaf(xv.x, w00, a); a = fmaf(xv.y, w01, a);
                a = fmaf(xv.z, w02, a); a = fmaf(xv.w, w03, a);
                a = fmaf(yv.x, w10, a); a = fmaf(yv.y, w11, a);
                a = fmaf(yv.z, w12, a); a = fmaf(yv.w, w13, a);
                accg[t] = a;
                float s = accs[t];
                s = fmaf(xv.x, l0, s); s = fmaf(xv.y, l1, s);
                s = fmaf(xv.z, l2, s); s = fmaf(xv.w, l3, s);
                accs[t] = s;
            }
        }
#pragma unroll
        for (int t = 0; t < 4; t++){
            int b = bbase + g + 4 * t;
            float xs = fmaf(scale_n, accs[t], lbs[o]);
            float sg = 1.f / (1.f + fast_exp(-xs));
            out[((size_t)b * NN + n) * 64 + o] = accg[t] + bias_s[o] + sg * xs;
        }
    }
}

// ---------------- launch ----------------
extern "C" void kernel_launch(void* const* d_in, const int* in_sizes, int n_in,
                              void* d_out, int out_size){
    const float* x   = (const float*)d_in[0];
    const float* E   = (const float*)d_in[1];
    const float* wp  = (const float*)d_in[2];
    const float* bp  = (const float*)d_in[3];
    const float* lw  = (const float*)d_in[4];
    const float* lb  = (const float*)d_in[5];
    const float* adj = (const float*)d_in[6];
    float* out = (float*)d_out;
    (void)in_sizes; (void)n_in; (void)out_size;

    cudaFuncSetAttribute(k_gemm_mma, cudaFuncAttributeMaxDynamicSharedMemorySize, GEMM_SMEM);
    cudaFuncSetAttribute(k_dyn,      cudaFuncAttributeMaxDynamicSharedMemorySize, DYN_SMEM);
    cudaFuncSetAttribute(k_final,    cudaFuncAttributeMaxDynamicSharedMemorySize, FIN_SMEM);

    k_zero    <<<16, 256>>>();
    k_rowsum  <<<NN, 256>>>(adj);
    k_scale   <<<NN / 16, 256>>>(adj);
    k_dyn     <<<NN / DYN_ROWS, 256, DYN_SMEM>>>(E);
    k_xsplit  <<<BB * 64, 256>>>(x);
    k_wgen    <<<dim3(16, 32), 256>>>(E, wp);
    k_gemm_mma<<<dim3(NBJ / 128, NN / 128), 256, GEMM_SMEM>>>();
    k_final   <<<NN, 256, FIN_SMEM>>>(x, E, bp, lw, lb, out);
}